// round 6
// baseline (speedup 1.0000x reference)
#include <cuda_runtime.h>
#include <math.h>
#include <stdint.h>

// ---------------- problem constants ----------------
#define NB   8
#define LSEQ 1024
#define SSEQ 2048
#define DIM  512
#define TOKD 256
#define KIN  1280
#define TOKS 10240

// ---------------- scratch ----------------
__device__ __align__(256) float g_Wc   [DIM * KIN];
__device__ __align__(256) float g_Wr   [4 * DIM * DIM];
__device__ __align__(256) float g_toksR[NB * TOKS * TOKD];
__device__ __align__(256) float g_latR [NB * LSEQ * DIM];
__device__ __align__(256) float g_tok  [NB * SSEQ * DIM];
__device__ __align__(256) float g_tokR [NB * SSEQ * DIM];
__device__ __align__(256) float g_Rlat [NB * LSEQ * DIM];
__device__ __align__(256) float g_Rtok [NB * SSEQ * DIM];
__device__ __align__(256) float g_Vlat [NB * LSEQ * DIM];
__device__ __align__(256) float g_Vtok [NB * SSEQ * DIM];
__device__ __align__(256) float g_VlatT[NB * DIM * LSEQ];
__device__ __align__(256) float g_VtokT[NB * DIM * SSEQ];
__device__ __align__(256) float g_S    [NB * LSEQ * SSEQ];
__device__ __align__(256) float g_PcT  [NB * SSEQ * LSEQ];
__device__ __align__(256) float g_rmax [NB * LSEQ];
__device__ __align__(256) float g_rinv [NB * LSEQ];
__device__ __align__(256) float g_cmax [NB * SSEQ];
__device__ __align__(256) float g_cinv [NB * SSEQ];
__device__ __align__(256) float g_pmax [NB * 8 * SSEQ];
__device__ __align__(256) float g_psum [NB * 8 * SSEQ];

// ---------------- GEMM config: 128x128 block, 4 warps, 64x64 warp tiles ----------------
#define BM 128
#define BN 128
#define BK 16
#define P0 20
#define STAGES 3
#define ASZ (BM * P0)
#define BSZ (BN * P0)
#define SM_BYTES (STAGES * (ASZ + BSZ) * 4)   // 61440

__device__ __forceinline__ uint32_t tf32r(float x) {
    uint32_t r;
    asm("cvt.rna.tf32.f32 %0, %1;" : "=r"(r) : "f"(x));
    return r;
}
__device__ __forceinline__ float tf32f(float x) { return __uint_as_float(tf32r(x)); }

__device__ __forceinline__ void mma_tf32(float c[4], const uint32_t a[4], const uint32_t b[2]) {
    asm volatile(
        "mma.sync.aligned.m16n8k8.row.col.f32.tf32.tf32.f32 "
        "{%0,%1,%2,%3}, {%4,%5,%6,%7}, {%8,%9}, {%0,%1,%2,%3};"
        : "+f"(c[0]), "+f"(c[1]), "+f"(c[2]), "+f"(c[3])
        : "r"(a[0]), "r"(a[1]), "r"(a[2]), "r"(a[3]), "r"(b[0]), "r"(b[1]));
}

__device__ __forceinline__ void cpasync16(void* dst, const void* src) {
    uint32_t d = (uint32_t)__cvta_generic_to_shared(dst);
    asm volatile("cp.async.cg.shared.global [%0], [%1], 16;" :: "r"(d), "l"(src));
}

// ---------------- TF32 GEMM: C(M,N) = alpha * A(M,K) @ B(N,K)^T ----------------
// A (M,K) k-major, B (N,K) k-major (both pre-rounded to tf32)
// EPI=0: C = alpha*acc
// EPI=1: v = acc + addend; store C and C2
// EPI=2: C = acc + bias (exact); C2 = tf32-rounded copy
// EPI=3: C = tf32-rounded(acc)
template<int EPI>
__global__ __launch_bounds__(128, 2) void k_gemm_tc(
    const float* __restrict__ A, const float* __restrict__ B,
    float* __restrict__ C, float* __restrict__ C2,
    int K, int lda, int ldb, int ldc,
    long long sA, long long sB, long long sC, long long sC2,
    float alpha, const float* __restrict__ bias,
    const float* __restrict__ addend, long long sAdd)
{
    extern __shared__ float sm[];
    float* As = sm;                      // STAGES * ASZ
    float* Bs = sm + STAGES * ASZ;       // STAGES * BSZ

    const long long z = blockIdx.z;
    A += z * sA;
    B += z * sB;
    C += z * sC;
    if (EPI == 1 || EPI == 2) C2 += z * sC2;
    if (EPI == 1) addend += z * sAdd;

    const int m0 = blockIdx.y * BM, n0 = blockIdx.x * BN;
    const int tid = threadIdx.x;
    const int wid = tid >> 5, lane = tid & 31;
    const int grp = lane >> 2, tig = lane & 3;
    const int wm = (wid >> 1) * 64, wn = (wid & 1) * 64;

    float acc[4][8][4];
#pragma unroll
    for (int i = 0; i < 4; i++)
#pragma unroll
        for (int j = 0; j < 8; j++)
#pragma unroll
            for (int r = 0; r < 4; r++) acc[i][j][r] = 0.f;

    auto loadTile = [&](int t, int buf) {
        const int k0 = t * BK;
        float* Ab = As + buf * ASZ;
        float* Bb = Bs + buf * BSZ;
#pragma unroll
        for (int i = 0; i < 4; i++) {
            int idx = i * 128 + tid;
            int row = idx >> 2, seg = idx & 3;
            cpasync16(Ab + row * P0 + seg * 4,
                      A + (long long)(m0 + row) * lda + k0 + seg * 4);
        }
#pragma unroll
        for (int i = 0; i < 4; i++) {
            int idx = i * 128 + tid;
            int row = idx >> 2, seg = idx & 3;
            cpasync16(Bb + row * P0 + seg * 4,
                      B + (long long)(n0 + row) * ldb + k0 + seg * 4);
        }
        asm volatile("cp.async.commit_group;");
    };

    auto compute = [&](int buf) {
        const float* Af = As + buf * ASZ;
        const float* Bf = Bs + buf * BSZ;
#pragma unroll
        for (int ks = 0; ks < BK; ks += 8) {
            uint32_t af[4][4], bf[8][2];
#pragma unroll
            for (int mi = 0; mi < 4; mi++) {
                const float* p = Af + (wm + mi * 16 + grp) * P0 + ks + tig;
                af[mi][0] = __float_as_uint(p[0]);
                af[mi][1] = __float_as_uint(p[8 * P0]);
                af[mi][2] = __float_as_uint(p[4]);
                af[mi][3] = __float_as_uint(p[8 * P0 + 4]);
            }
#pragma unroll
            for (int ni = 0; ni < 8; ni++) {
                const float* p = Bf + (wn + ni * 8 + grp) * P0 + ks + tig;
                bf[ni][0] = __float_as_uint(p[0]);
                bf[ni][1] = __float_as_uint(p[4]);
            }
#pragma unroll
            for (int mi = 0; mi < 4; mi++)
#pragma unroll
                for (int ni = 0; ni < 8; ni++)
                    mma_tf32(acc[mi][ni], af[mi], bf[ni]);
        }
    };

    const int tiles = K / BK;
#pragma unroll
    for (int s = 0; s < STAGES - 1; s++) loadTile(s, s);
    for (int t = 0; t < tiles; t++) {
        asm volatile("cp.async.wait_group %0;" :: "n"(STAGES - 2));
        __syncthreads();
        if (t + STAGES - 1 < tiles) loadTile(t + STAGES - 1, (t + STAGES - 1) % STAGES);
        compute(t % STAGES);
    }

    // epilogue
#pragma unroll
    for (int mi = 0; mi < 4; mi++) {
        const int r = m0 + wm + mi * 16 + grp;
#pragma unroll
        for (int ni = 0; ni < 8; ni++) {
            const int c = n0 + wn + ni * 8 + tig * 2;
            float2 v0 = {acc[mi][ni][0], acc[mi][ni][1]};
            float2 v1 = {acc[mi][ni][2], acc[mi][ni][3]};
            if (EPI == 0 || EPI == 3) {
                v0.x *= alpha; v0.y *= alpha; v1.x *= alpha; v1.y *= alpha;
                if (EPI == 3) {
                    v0.x = tf32f(v0.x); v0.y = tf32f(v0.y);
                    v1.x = tf32f(v1.x); v1.y = tf32f(v1.y);
                }
                *(float2*)(C + (long long)r * ldc + c) = v0;
                *(float2*)(C + (long long)(r + 8) * ldc + c) = v1;
            } else if (EPI == 2) {
                float bx = bias[c], by = bias[c + 1];
                v0.x += bx; v0.y += by; v1.x += bx; v1.y += by;
                *(float2*)(C + (long long)r * ldc + c) = v0;
                *(float2*)(C + (long long)(r + 8) * ldc + c) = v1;
                float2 r0 = {tf32f(v0.x), tf32f(v0.y)};
                float2 r1 = {tf32f(v1.x), tf32f(v1.y)};
                *(float2*)(C2 + (long long)r * ldc + c) = r0;
                *(float2*)(C2 + (long long)(r + 8) * ldc + c) = r1;
            } else {   // EPI == 1
                float2 a0 = *(const float2*)(addend + (long long)r * ldc + c);
                float2 a1 = *(const float2*)(addend + (long long)(r + 8) * ldc + c);
                v0.x += a0.x; v0.y += a0.y;
                v1.x += a1.x; v1.y += a1.y;
                *(float2*)(C  + (long long)r * ldc + c) = v0;
                *(float2*)(C  + (long long)(r + 8) * ldc + c) = v1;
                *(float2*)(C2 + (long long)r * ldc + c) = v0;
                *(float2*)(C2 + (long long)(r + 8) * ldc + c) = v1;
            }
        }
    }
}

// ---------------- prep kernels ----------------
__global__ void k_prep_w(const float* __restrict__ w, float* __restrict__ wc) {
    int i = blockIdx.x * 256 + threadIdx.x;
    if (i < DIM * KIN) {
        int e = i / KIN;
        int r = i - e * KIN;
        int t = r / TOKD;
        int c = r - t * TOKD;
        wc[i] = tf32f(w[e * KIN + c * 5 + t]);
    }
}
__global__ void k_round_w(const float* __restrict__ w0, const float* __restrict__ w1,
                          const float* __restrict__ w2, const float* __restrict__ w3,
                          float* __restrict__ out) {
    int i = blockIdx.x * 256 + threadIdx.x;
    if (i < DIM * DIM) {
        out[i]                 = tf32f(w0[i]);
        out[i + DIM * DIM]     = tf32f(w1[i]);
        out[i + 2 * DIM * DIM] = tf32f(w2[i]);
        out[i + 3 * DIM * DIM] = tf32f(w3[i]);
    }
}
__global__ void k_round_copy(const float* __restrict__ s, float* __restrict__ d, long long n) {
    long long i = ((long long)blockIdx.x * 256 + threadIdx.x) * 4;
    if (i < n) {
        float4 v = *(const float4*)(s + i);
        v.x = tf32f(v.x); v.y = tf32f(v.y); v.z = tf32f(v.z); v.w = tf32f(v.w);
        *(float4*)(d + i) = v;
    }
}

// transpose per batch: src (R,C) -> dst (C,R)
__global__ __launch_bounds__(256) void k_transpose(const float* __restrict__ src,
                                                   float* __restrict__ dst, int R, int C) {
    __shared__ float tile[32][33];
    const int b = blockIdx.z;
    src += (long long)b * R * C;
    dst += (long long)b * R * C;
    const int c0 = blockIdx.x * 32, r0 = blockIdx.y * 32;
    const int tx = threadIdx.x & 31, ty = threadIdx.x >> 5;
#pragma unroll
    for (int i = 0; i < 4; i++)
        tile[ty + i * 8][tx] = src[(long long)(r0 + ty + i * 8) * C + c0 + tx];
    __syncthreads();
#pragma unroll
    for (int i = 0; i < 4; i++)
        dst[(long long)(c0 + ty + i * 8) * R + r0 + tx] = tile[tx][ty + i * 8];
}

// ---------------- softmax stats ----------------
__global__ void k_row_stats(const float* __restrict__ A,
                            float* __restrict__ rmax, float* __restrict__ rinv) {
    __shared__ float red[256];
    long long r = blockIdx.x;
    const float* row = A + r * SSEQ;
    int tid = threadIdx.x;
    float m = -1e30f;
    for (int c = tid; c < SSEQ; c += 256) m = fmaxf(m, row[c]);
    red[tid] = m; __syncthreads();
    for (int s = 128; s > 0; s >>= 1) {
        if (tid < s) red[tid] = fmaxf(red[tid], red[tid + s]);
        __syncthreads();
    }
    m = red[0];
    __syncthreads();
    float sum = 0.f;
    for (int c = tid; c < SSEQ; c += 256) sum += __expf(row[c] - m);
    red[tid] = sum; __syncthreads();
    for (int s = 128; s > 0; s >>= 1) {
        if (tid < s) red[tid] += red[tid + s];
        __syncthreads();
    }
    if (tid == 0) { rmax[r] = m; rinv[r] = 1.f / red[0]; }
}

__global__ void k_col_part(const float* __restrict__ A,
                           float* __restrict__ pmax, float* __restrict__ psum) {
    const int b = blockIdx.z, ch = blockIdx.y;
    const int s = blockIdx.x * 256 + threadIdx.x;
    const float* Ab = A + (long long)b * LSEQ * SSEQ + (long long)ch * 128 * SSEQ + s;
    float m = -1e30f, sum = 0.f;
#pragma unroll 4
    for (int l = 0; l < 128; l++) {
        float v = Ab[(long long)l * SSEQ];
        float mn = fmaxf(m, v);
        sum = sum * __expf(m - mn) + __expf(v - mn);
        m = mn;
    }
    pmax[(b * 8 + ch) * SSEQ + s] = m;
    psum[(b * 8 + ch) * SSEQ + s] = sum;
}
__global__ void k_col_comb(const float* __restrict__ pmax, const float* __restrict__ psum,
                           float* __restrict__ cmax, float* __restrict__ cinv) {
    const int b = blockIdx.y;
    const int s = blockIdx.x * 256 + threadIdx.x;
    float m = -1e30f;
#pragma unroll
    for (int c = 0; c < 8; c++) m = fmaxf(m, pmax[(b * 8 + c) * SSEQ + s]);
    float sum = 0.f;
#pragma unroll
    for (int c = 0; c < 8; c++)
        sum += psum[(b * 8 + c) * SSEQ + s] * __expf(pmax[(b * 8 + c) * SSEQ + s] - m);
    cmax[b * SSEQ + s] = m;
    cinv[b * SSEQ + s] = 1.f / sum;
}

// ---------------- apply both softmaxes ----------------
__global__ __launch_bounds__(256) void k_softmax_apply(
    float* __restrict__ A, float* __restrict__ PcT,
    const float* __restrict__ rmax, const float* __restrict__ rinv,
    const float* __restrict__ cmax, const float* __restrict__ cinv)
{
    __shared__ float tile[32][33];
    const int b = blockIdx.z;
    const int s0 = blockIdx.x * 32, l0 = blockIdx.y * 32;
    float* Ab = A + (long long)b * LSEQ * SSEQ;
    float* Pb = PcT + (long long)b * SSEQ * LSEQ;
    const int tx = threadIdx.x & 31, ty = threadIdx.x >> 5;

    const float cm = cmax[b * SSEQ + s0 + tx];
    const float ci = cinv[b * SSEQ + s0 + tx];
#pragma unroll
    for (int i = 0; i < 4; i++) {
        const int l = l0 + ty + i * 8;
        float v = Ab[(long long)l * SSEQ + s0 + tx];
        Ab[(long long)l * SSEQ + s0 + tx] = tf32f(__expf(v - rmax[b * LSEQ + l]) * rinv[b * LSEQ + l]);
        tile[ty + i * 8][tx] = tf32f(__expf(v - cm) * ci);
    }
    __syncthreads();
#pragma unroll
    for (int i = 0; i < 4; i++) {
        const int s = s0 + ty + i * 8;
        Pb[(long long)s * LSEQ + l0 + tx] = tile[tx][ty + i * 8];
    }
}

// ---------------- launch ----------------
extern "C" void kernel_launch(void* const* d_in, const int* in_sizes, int n_in,
                              void* d_out, int out_size) {
    const float* latents = (const float*)d_in[0];
    const float* tokens  = (const float*)d_in[1];
    const float* W_lat   = (const float*)d_in[2];
    const float* W_tok   = (const float*)d_in[3];
    const float* W_vlat  = (const float*)d_in[4];
    const float* W_vtok  = (const float*)d_in[5];
    const float* conv_w  = (const float*)d_in[6];
    const float* conv_b  = (const float*)d_in[7];
    float* out = (float*)d_out;

    float *wc, *wr, *toksR, *latR, *tok, *tokR, *rlat, *rtok, *vlat, *vtok;
    float *vlatT, *vtokT, *smat, *pct, *rmax, *rinv, *cmax, *cinv, *pmax, *psum;
    cudaGetSymbolAddress((void**)&wc,    g_Wc);
    cudaGetSymbolAddress((void**)&wr,    g_Wr);
    cudaGetSymbolAddress((void**)&toksR, g_toksR);
    cudaGetSymbolAddress((void**)&latR,  g_latR);
    cudaGetSymbolAddress((void**)&tok,   g_tok);
    cudaGetSymbolAddress((void**)&tokR,  g_tokR);
    cudaGetSymbolAddress((void**)&rlat,  g_Rlat);
    cudaGetSymbolAddress((void**)&rtok,  g_Rtok);
    cudaGetSymbolAddress((void**)&vlat,  g_Vlat);
    cudaGetSymbolAddress((void**)&vtok,  g_Vtok);
    cudaGetSymbolAddress((void**)&vlatT, g_VlatT);
    cudaGetSymbolAddress((void**)&vtokT, g_VtokT);
    cudaGetSymbolAddress((void**)&smat,  g_S);
    cudaGetSymbolAddress((void**)&pct,   g_PcT);
    cudaGetSymbolAddress((void**)&rmax,  g_rmax);
    cudaGetSymbolAddress((void**)&rinv,  g_rinv);
    cudaGetSymbolAddress((void**)&cmax,  g_cmax);
    cudaGetSymbolAddress((void**)&cinv,  g_cinv);
    cudaGetSymbolAddress((void**)&pmax,  g_pmax);
    cudaGetSymbolAddress((void**)&psum,  g_psum);

    cudaFuncSetAttribute(k_gemm_tc<0>, cudaFuncAttributeMaxDynamicSharedMemorySize, SM_BYTES);
    cudaFuncSetAttribute(k_gemm_tc<1>, cudaFuncAttributeMaxDynamicSharedMemorySize, SM_BYTES);
    cudaFuncSetAttribute(k_gemm_tc<2>, cudaFuncAttributeMaxDynamicSharedMemorySize, SM_BYTES);
    cudaFuncSetAttribute(k_gemm_tc<3>, cudaFuncAttributeMaxDynamicSharedMemorySize, SM_BYTES);

    const long long UL = (long long)NB * LSEQ * DIM;
    const long long UT = (long long)NB * SSEQ * DIM;
    const long long CONCAT = UL + UT;

    // pre-round inputs feeding GEMM operands
    const long long NTOK = (long long)NB * TOKS * TOKD;
    const long long NLAT = (long long)NB * LSEQ * DIM;
    k_round_copy<<<(int)(NTOK / 4 / 256), 256>>>(tokens, toksR, NTOK);
    k_round_copy<<<(int)(NLAT / 4 / 256), 256>>>(latents, latR, NLAT);
    k_prep_w<<<(DIM * KIN + 255) / 256, 256>>>(conv_w, wc);
    k_round_w<<<(DIM * DIM + 255) / 256, 256>>>(W_lat, W_tok, W_vlat, W_vtok, wr);

    // conv as GEMM: tok (exact, +bias) and tokR (rounded)
    k_gemm_tc<2><<<dim3(DIM / BN, (NB * SSEQ) / BM, 1), 128, SM_BYTES>>>(
        toksR, wc, tok, tokR, KIN, KIN, KIN, DIM, 0, 0, 0, 0,
        1.f, conv_b, nullptr, 0);

    // projections -> rounded
    k_gemm_tc<3><<<dim3(DIM / BN, (NB * LSEQ) / BM, 1), 128, SM_BYTES>>>(
        latR, wr + 0 * DIM * DIM, rlat, nullptr, DIM, DIM, DIM, DIM, 0, 0, 0, 0,
        1.f, nullptr, nullptr, 0);
    k_gemm_tc<3><<<dim3(DIM / BN, (NB * LSEQ) / BM, 1), 128, SM_BYTES>>>(
        latR, wr + 2 * DIM * DIM, vlat, nullptr, DIM, DIM, DIM, DIM, 0, 0, 0, 0,
        1.f, nullptr, nullptr, 0);
    k_gemm_tc<3><<<dim3(DIM / BN, (NB * SSEQ) / BM, 1), 128, SM_BYTES>>>(
        tokR, wr + 1 * DIM * DIM, rtok, nullptr, DIM, DIM, DIM, DIM, 0, 0, 0, 0,
        1.f, nullptr, nullptr, 0);
    k_gemm_tc<3><<<dim3(DIM / BN, (NB * SSEQ) / BM, 1), 128, SM_BYTES>>>(
        tokR, wr + 3 * DIM * DIM, vtok, nullptr, DIM, DIM, DIM, DIM, 0, 0, 0, 0,
        1.f, nullptr, nullptr, 0);

    // V transposes: (seq, E) -> (E, seq)
    k_transpose<<<dim3(DIM / 32, LSEQ / 32, NB), 256>>>(vlat, vlatT, LSEQ, DIM);
    k_transpose<<<dim3(DIM / 32, SSEQ / 32, NB), 256>>>(vtok, vtokT, SSEQ, DIM);

    // scores: A = Rlat @ Rtok^T / sqrt(512)
    const float scale = 0.044194173824159216f;
    k_gemm_tc<0><<<dim3(SSEQ / BN, LSEQ / BM, NB), 128, SM_BYTES>>>(
        rlat, rtok, smat, nullptr, DIM, DIM, DIM, SSEQ,
        (long long)LSEQ * DIM, (long long)SSEQ * DIM, (long long)LSEQ * SSEQ, 0,
        scale, nullptr, nullptr, 0);

    // softmax stats + apply
    k_row_stats<<<NB * LSEQ, 256>>>(smat, rmax, rinv);
    k_col_part<<<dim3(SSEQ / 256, 8, NB), 256>>>(smat, pmax, psum);
    k_col_comb<<<dim3(SSEQ / 256, NB), 256>>>(pmax, psum, cmax, cinv);
    k_softmax_apply<<<dim3(SSEQ / 32, LSEQ / 32, NB), 256>>>(
        smat, pct, rmax, rinv, cmax, cinv);

    // delta_lat = Prow @ VtokT^T + latents   (B = VtokT (512,2048) k-major)
    k_gemm_tc<1><<<dim3(DIM / BN, LSEQ / BM, NB), 128, SM_BYTES>>>(
        smat, vtokT, out, out + CONCAT, SSEQ, SSEQ, SSEQ, DIM,
        (long long)LSEQ * SSEQ, (long long)DIM * SSEQ,
        (long long)LSEQ * DIM, (long long)(LSEQ + SSEQ) * DIM,
        1.f, nullptr, latents, (long long)LSEQ * DIM);

    // delta_tok = PcT @ VlatT^T + tok        (B = VlatT (512,1024) k-major)
    k_gemm_tc<1><<<dim3(DIM / BN, SSEQ / BM, NB), 128, SM_BYTES>>>(
        pct, vlatT, out + UL, out + CONCAT + (long long)LSEQ * DIM, LSEQ, LSEQ, LSEQ, DIM,
        (long long)SSEQ * LSEQ, (long long)DIM * LSEQ,
        (long long)SSEQ * DIM, (long long)(LSEQ + SSEQ) * DIM,
        1.f, nullptr, tok, (long long)SSEQ * DIM);
}

// round 7
// speedup vs baseline: 1.7057x; 1.7057x over previous
#include <cuda_runtime.h>
#include <cuda_fp16.h>
#include <math.h>
#include <stdint.h>

// ---------------- problem constants ----------------
#define NB   8
#define LSEQ 1024
#define SSEQ 2048
#define DIM  512
#define TOKD 256
#define KIN  1280
#define TOKS 10240

// ---------------- scratch ----------------
__device__ __align__(256) __half g_WcH  [DIM * KIN];
__device__ __align__(256) __half g_WrH  [4 * DIM * DIM];
__device__ __align__(256) __half g_toksH[NB * TOKS * TOKD];
__device__ __align__(256) __half g_latH [NB * LSEQ * DIM];
__device__ __align__(256) float  g_tok  [NB * SSEQ * DIM];   // conv out exact (residual)
__device__ __align__(256) __half g_tokH [NB * SSEQ * DIM];
__device__ __align__(256) __half g_RlatH[NB * LSEQ * DIM];
__device__ __align__(256) __half g_RtokH[NB * SSEQ * DIM];
__device__ __align__(256) __half g_VlatH[NB * LSEQ * DIM];
__device__ __align__(256) __half g_VtokH[NB * SSEQ * DIM];
__device__ __align__(256) __half g_VlatT[NB * DIM * LSEQ];   // (E, L)
__device__ __align__(256) __half g_VtokT[NB * DIM * SSEQ];   // (E, S)
__device__ __align__(256) float  g_S    [NB * LSEQ * SSEQ];  // scores f32
__device__ __align__(256) __half g_PrH  [NB * LSEQ * SSEQ];  // row-softmax (L,S)
__device__ __align__(256) __half g_PcTH [NB * SSEQ * LSEQ];  // col-softmax^T (S,L)
__device__ __align__(256) float  g_rmax [NB * LSEQ];
__device__ __align__(256) float  g_rinv [NB * LSEQ];
__device__ __align__(256) float  g_cmax [NB * SSEQ];
__device__ __align__(256) float  g_cinv [NB * SSEQ];
__device__ __align__(256) float  g_pmax [NB * 8 * SSEQ];
__device__ __align__(256) float  g_psum [NB * 8 * SSEQ];

// ---------------- GEMM config: 128x128 block, 4 warps (64x64 each), fp16 k16 MMA ----------------
#define BM 128
#define BN 128
#define BK 32
#define PH 40                       // halves per smem row (conflict-free frag LDS)
#define STAGES 3
#define ASZH (BM * PH)              // 5120 halves / stage
#define BSZH (BN * PH)
#define SM_BYTES (STAGES * (ASZH + BSZH) * 2)   // 61440

__device__ __forceinline__ void mma_f16(float c[4], const uint32_t a[4], const uint32_t b[2]) {
    asm volatile(
        "mma.sync.aligned.m16n8k16.row.col.f32.f16.f16.f32 "
        "{%0,%1,%2,%3}, {%4,%5,%6,%7}, {%8,%9}, {%0,%1,%2,%3};"
        : "+f"(c[0]), "+f"(c[1]), "+f"(c[2]), "+f"(c[3])
        : "r"(a[0]), "r"(a[1]), "r"(a[2]), "r"(a[3]), "r"(b[0]), "r"(b[1]));
}

__device__ __forceinline__ void cpasync16(void* dst, const void* src) {
    uint32_t d = (uint32_t)__cvta_generic_to_shared(dst);
    asm volatile("cp.async.cg.shared.global [%0], [%1], 16;" :: "r"(d), "l"(src));
}

// ---------------- fp16 GEMM: acc(M,N) = A(M,K) @ B(N,K)^T, fp32 accumulate ----------------
// EPI=0: Cf = alpha*acc
// EPI=1: v = acc + addend; store Cf and Cf2
// EPI=2: Cf = acc + bias; Ch = half(Cf)
// EPI=3: Ch = half(acc)
template<int EPI>
__global__ __launch_bounds__(128, 2) void k_gemm_h(
    const __half* __restrict__ A, const __half* __restrict__ B,
    float* __restrict__ Cf, float* __restrict__ Cf2, __half* __restrict__ Ch,
    int K, int lda, int ldb, int ldc,
    long long sA, long long sB, long long sC, long long sC2,
    float alpha, const float* __restrict__ bias,
    const float* __restrict__ addend, long long sAdd)
{
    extern __shared__ __half smh[];
    __half* As = smh;
    __half* Bs = smh + STAGES * ASZH;

    const long long z = blockIdx.z;
    A += z * sA;
    B += z * sB;
    if (EPI == 0 || EPI == 1 || EPI == 2) Cf += z * sC;
    if (EPI == 1) { Cf2 += z * sC2; addend += z * sAdd; }
    if (EPI == 2 || EPI == 3) Ch += z * sC;

    const int m0 = blockIdx.y * BM, n0 = blockIdx.x * BN;
    const int tid = threadIdx.x;
    const int wid = tid >> 5, lane = tid & 31;
    const int grp = lane >> 2, tig = lane & 3;
    const int wm = (wid >> 1) * 64, wn = (wid & 1) * 64;

    float acc[4][8][4];
#pragma unroll
    for (int i = 0; i < 4; i++)
#pragma unroll
        for (int j = 0; j < 8; j++)
#pragma unroll
            for (int r = 0; r < 4; r++) acc[i][j][r] = 0.f;

    auto loadTile = [&](int t, int buf) {
        const int k0 = t * BK;
        __half* Ab = As + buf * ASZH;
        __half* Bb = Bs + buf * BSZH;
#pragma unroll
        for (int i = 0; i < 4; i++) {               // A: 128 rows x 64B (4 x 16B chunks)
            int idx = i * 128 + tid;
            int row = idx >> 2, seg = idx & 3;
            cpasync16(Ab + row * PH + seg * 8,
                      A + (long long)(m0 + row) * lda + k0 + seg * 8);
        }
#pragma unroll
        for (int i = 0; i < 4; i++) {
            int idx = i * 128 + tid;
            int row = idx >> 2, seg = idx & 3;
            cpasync16(Bb + row * PH + seg * 8,
                      B + (long long)(n0 + row) * ldb + k0 + seg * 8);
        }
        asm volatile("cp.async.commit_group;");
    };

    auto compute = [&](int buf) {
        const uint32_t* Au = (const uint32_t*)(As + buf * ASZH);   // row stride 20 u32
        const uint32_t* Bu = (const uint32_t*)(Bs + buf * BSZH);
#pragma unroll
        for (int ks = 0; ks < 2; ks++) {            // two k16 steps
            uint32_t af[4][4], bf[8][2];
#pragma unroll
            for (int mi = 0; mi < 4; mi++) {
                const uint32_t* p = Au + (wm + mi * 16 + grp) * (PH / 2) + ks * 8 + tig;
                af[mi][0] = p[0];
                af[mi][1] = p[8 * (PH / 2)];
                af[mi][2] = p[4];
                af[mi][3] = p[8 * (PH / 2) + 4];
            }
#pragma unroll
            for (int ni = 0; ni < 8; ni++) {
                const uint32_t* q = Bu + (wn + ni * 8 + grp) * (PH / 2) + ks * 8 + tig;
                bf[ni][0] = q[0];
                bf[ni][1] = q[4];
            }
#pragma unroll
            for (int mi = 0; mi < 4; mi++)
#pragma unroll
                for (int ni = 0; ni < 8; ni++)
                    mma_f16(acc[mi][ni], af[mi], bf[ni]);
        }
    };

    const int tiles = K / BK;
#pragma unroll
    for (int s = 0; s < STAGES - 1; s++) loadTile(s, s);
    for (int t = 0; t < tiles; t++) {
        asm volatile("cp.async.wait_group %0;" :: "n"(STAGES - 2));
        __syncthreads();
        if (t + STAGES - 1 < tiles) loadTile(t + STAGES - 1, (t + STAGES - 1) % STAGES);
        compute(t % STAGES);
    }

    // epilogue
#pragma unroll
    for (int mi = 0; mi < 4; mi++) {
        const int r = m0 + wm + mi * 16 + grp;
#pragma unroll
        for (int ni = 0; ni < 8; ni++) {
            const int c = n0 + wn + ni * 8 + tig * 2;
            float2 v0 = {acc[mi][ni][0], acc[mi][ni][1]};
            float2 v1 = {acc[mi][ni][2], acc[mi][ni][3]};
            if (EPI == 0) {
                v0.x *= alpha; v0.y *= alpha; v1.x *= alpha; v1.y *= alpha;
                *(float2*)(Cf + (long long)r * ldc + c) = v0;
                *(float2*)(Cf + (long long)(r + 8) * ldc + c) = v1;
            } else if (EPI == 3) {
                *(__half2*)(Ch + (long long)r * ldc + c) = __floats2half2_rn(v0.x, v0.y);
                *(__half2*)(Ch + (long long)(r + 8) * ldc + c) = __floats2half2_rn(v1.x, v1.y);
            } else if (EPI == 2) {
                float bx = bias[c], by = bias[c + 1];
                v0.x += bx; v0.y += by; v1.x += bx; v1.y += by;
                *(float2*)(Cf + (long long)r * ldc + c) = v0;
                *(float2*)(Cf + (long long)(r + 8) * ldc + c) = v1;
                *(__half2*)(Ch + (long long)r * ldc + c) = __floats2half2_rn(v0.x, v0.y);
                *(__half2*)(Ch + (long long)(r + 8) * ldc + c) = __floats2half2_rn(v1.x, v1.y);
            } else {   // EPI == 1
                float2 a0 = *(const float2*)(addend + (long long)r * ldc + c);
                float2 a1 = *(const float2*)(addend + (long long)(r + 8) * ldc + c);
                v0.x += a0.x; v0.y += a0.y;
                v1.x += a1.x; v1.y += a1.y;
                *(float2*)(Cf  + (long long)r * ldc + c) = v0;
                *(float2*)(Cf  + (long long)(r + 8) * ldc + c) = v1;
                *(float2*)(Cf2 + (long long)r * ldc + c) = v0;
                *(float2*)(Cf2 + (long long)(r + 8) * ldc + c) = v1;
            }
        }
    }
}

// ---------------- prep kernels ----------------
__global__ void k_prep_w(const float* __restrict__ w, __half* __restrict__ wc) {
    int i = blockIdx.x * 256 + threadIdx.x;
    if (i < DIM * KIN) {
        int e = i / KIN;
        int r = i - e * KIN;
        int t = r / TOKD;
        int c = r - t * TOKD;
        wc[i] = __float2half_rn(w[e * KIN + c * 5 + t]);
    }
}
__global__ void k_prep_wr(const float* __restrict__ w0, const float* __restrict__ w1,
                          const float* __restrict__ w2, const float* __restrict__ w3,
                          __half* __restrict__ out) {
    int i = blockIdx.x * 256 + threadIdx.x;
    if (i < DIM * DIM) {
        out[i]                 = __float2half_rn(w0[i]);
        out[i + DIM * DIM]     = __float2half_rn(w1[i]);
        out[i + 2 * DIM * DIM] = __float2half_rn(w2[i]);
        out[i + 3 * DIM * DIM] = __float2half_rn(w3[i]);
    }
}
__global__ void k_tohalf(const float* __restrict__ s, __half* __restrict__ d, long long n) {
    long long i = ((long long)blockIdx.x * 256 + threadIdx.x) * 4;
    if (i < n) {
        float4 v = *(const float4*)(s + i);
        *(__half2*)(d + i)     = __floats2half2_rn(v.x, v.y);
        *(__half2*)(d + i + 2) = __floats2half2_rn(v.z, v.w);
    }
}

// transpose per batch (half): src (R,C) -> dst (C,R)
__global__ __launch_bounds__(256) void k_transpose_h(const __half* __restrict__ src,
                                                     __half* __restrict__ dst, int R, int C) {
    __shared__ __half tile[32][34];
    const int b = blockIdx.z;
    src += (long long)b * R * C;
    dst += (long long)b * R * C;
    const int c0 = blockIdx.x * 32, r0 = blockIdx.y * 32;
    const int tx = threadIdx.x & 31, ty = threadIdx.x >> 5;
#pragma unroll
    for (int i = 0; i < 4; i++)
        tile[ty + i * 8][tx] = src[(long long)(r0 + ty + i * 8) * C + c0 + tx];
    __syncthreads();
#pragma unroll
    for (int i = 0; i < 4; i++)
        dst[(long long)(c0 + ty + i * 8) * R + r0 + tx] = tile[tx][ty + i * 8];
}

// ---------------- softmax stats ----------------
__global__ void k_row_stats(const float* __restrict__ A,
                            float* __restrict__ rmax, float* __restrict__ rinv) {
    __shared__ float red[256];
    long long r = blockIdx.x;
    const float* row = A + r * SSEQ;
    int tid = threadIdx.x;
    float m = -1e30f;
    for (int c = tid; c < SSEQ; c += 256) m = fmaxf(m, row[c]);
    red[tid] = m; __syncthreads();
    for (int s = 128; s > 0; s >>= 1) {
        if (tid < s) red[tid] = fmaxf(red[tid], red[tid + s]);
        __syncthreads();
    }
    m = red[0];
    __syncthreads();
    float sum = 0.f;
    for (int c = tid; c < SSEQ; c += 256) sum += __expf(row[c] - m);
    red[tid] = sum; __syncthreads();
    for (int s = 128; s > 0; s >>= 1) {
        if (tid < s) red[tid] += red[tid + s];
        __syncthreads();
    }
    if (tid == 0) { rmax[r] = m; rinv[r] = 1.f / red[0]; }
}

__global__ void k_col_part(const float* __restrict__ A,
                           float* __restrict__ pmax, float* __restrict__ psum) {
    const int b = blockIdx.z, ch = blockIdx.y;
    const int s = blockIdx.x * 256 + threadIdx.x;
    const float* Ab = A + (long long)b * LSEQ * SSEQ + (long long)ch * 128 * SSEQ + s;
    float m = -1e30f, sum = 0.f;
#pragma unroll 4
    for (int l = 0; l < 128; l++) {
        float v = Ab[(long long)l * SSEQ];
        float mn = fmaxf(m, v);
        sum = sum * __expf(m - mn) + __expf(v - mn);
        m = mn;
    }
    pmax[(b * 8 + ch) * SSEQ + s] = m;
    psum[(b * 8 + ch) * SSEQ + s] = sum;
}
__global__ void k_col_comb(const float* __restrict__ pmax, const float* __restrict__ psum,
                           float* __restrict__ cmax, float* __restrict__ cinv) {
    const int b = blockIdx.y;
    const int s = blockIdx.x * 256 + threadIdx.x;
    float m = -1e30f;
#pragma unroll
    for (int c = 0; c < 8; c++) m = fmaxf(m, pmax[(b * 8 + c) * SSEQ + s]);
    float sum = 0.f;
#pragma unroll
    for (int c = 0; c < 8; c++)
        sum += psum[(b * 8 + c) * SSEQ + s] * __expf(pmax[(b * 8 + c) * SSEQ + s] - m);
    cmax[b * SSEQ + s] = m;
    cinv[b * SSEQ + s] = 1.f / sum;
}

// ---------------- apply both softmaxes -> half ----------------
__global__ __launch_bounds__(256) void k_softmax_apply(
    const float* __restrict__ A, __half* __restrict__ Pr, __half* __restrict__ PcT,
    const float* __restrict__ rmax, const float* __restrict__ rinv,
    const float* __restrict__ cmax, const float* __restrict__ cinv)
{
    __shared__ float tile[32][33];
    const int b = blockIdx.z;
    const int s0 = blockIdx.x * 32, l0 = blockIdx.y * 32;
    const float* Ab = A + (long long)b * LSEQ * SSEQ;
    __half* Prb = Pr + (long long)b * LSEQ * SSEQ;
    __half* Pcb = PcT + (long long)b * SSEQ * LSEQ;
    const int tx = threadIdx.x & 31, ty = threadIdx.x >> 5;

    const float cm = cmax[b * SSEQ + s0 + tx];
    const float ci = cinv[b * SSEQ + s0 + tx];
#pragma unroll
    for (int i = 0; i < 4; i++) {
        const int l = l0 + ty + i * 8;
        float v = Ab[(long long)l * SSEQ + s0 + tx];
        Prb[(long long)l * SSEQ + s0 + tx] =
            __float2half_rn(__expf(v - rmax[b * LSEQ + l]) * rinv[b * LSEQ + l]);
        tile[ty + i * 8][tx] = __expf(v - cm) * ci;
    }
    __syncthreads();
#pragma unroll
    for (int i = 0; i < 4; i++) {
        const int s = s0 + ty + i * 8;
        Pcb[(long long)s * LSEQ + l0 + tx] = __float2half_rn(tile[tx][ty + i * 8]);
    }
}

// ---------------- launch ----------------
extern "C" void kernel_launch(void* const* d_in, const int* in_sizes, int n_in,
                              void* d_out, int out_size) {
    const float* latents = (const float*)d_in[0];
    const float* tokens  = (const float*)d_in[1];
    const float* W_lat   = (const float*)d_in[2];
    const float* W_tok   = (const float*)d_in[3];
    const float* W_vlat  = (const float*)d_in[4];
    const float* W_vtok  = (const float*)d_in[5];
    const float* conv_w  = (const float*)d_in[6];
    const float* conv_b  = (const float*)d_in[7];
    float* out = (float*)d_out;

    __half *wcH, *wrH, *toksH, *latH, *tokH, *rlatH, *rtokH, *vlatH, *vtokH, *vlatT, *vtokT, *prH, *pcTH;
    float *tok, *smat, *rmax, *rinv, *cmax, *cinv, *pmax, *psum;
    cudaGetSymbolAddress((void**)&wcH,   g_WcH);
    cudaGetSymbolAddress((void**)&wrH,   g_WrH);
    cudaGetSymbolAddress((void**)&toksH, g_toksH);
    cudaGetSymbolAddress((void**)&latH,  g_latH);
    cudaGetSymbolAddress((void**)&tok,   g_tok);
    cudaGetSymbolAddress((void**)&tokH,  g_tokH);
    cudaGetSymbolAddress((void**)&rlatH, g_RlatH);
    cudaGetSymbolAddress((void**)&rtokH, g_RtokH);
    cudaGetSymbolAddress((void**)&vlatH, g_VlatH);
    cudaGetSymbolAddress((void**)&vtokH, g_VtokH);
    cudaGetSymbolAddress((void**)&vlatT, g_VlatT);
    cudaGetSymbolAddress((void**)&vtokT, g_VtokT);
    cudaGetSymbolAddress((void**)&prH,   g_PrH);
    cudaGetSymbolAddress((void**)&pcTH,  g_PcTH);
    cudaGetSymbolAddress((void**)&smat,  g_S);
    cudaGetSymbolAddress((void**)&rmax,  g_rmax);
    cudaGetSymbolAddress((void**)&rinv,  g_rinv);
    cudaGetSymbolAddress((void**)&cmax,  g_cmax);
    cudaGetSymbolAddress((void**)&cinv,  g_cinv);
    cudaGetSymbolAddress((void**)&pmax,  g_pmax);
    cudaGetSymbolAddress((void**)&psum,  g_psum);

    cudaFuncSetAttribute(k_gemm_h<0>, cudaFuncAttributeMaxDynamicSharedMemorySize, SM_BYTES);
    cudaFuncSetAttribute(k_gemm_h<1>, cudaFuncAttributeMaxDynamicSharedMemorySize, SM_BYTES);
    cudaFuncSetAttribute(k_gemm_h<2>, cudaFuncAttributeMaxDynamicSharedMemorySize, SM_BYTES);
    cudaFuncSetAttribute(k_gemm_h<3>, cudaFuncAttributeMaxDynamicSharedMemorySize, SM_BYTES);

    const long long UL = (long long)NB * LSEQ * DIM;
    const long long UT = (long long)NB * SSEQ * DIM;
    const long long CONCAT = UL + UT;

    // inputs -> half
    const long long NTOK = (long long)NB * TOKS * TOKD;
    const long long NLAT = (long long)NB * LSEQ * DIM;
    k_tohalf<<<(int)(NTOK / 4 / 256), 256>>>(tokens, toksH, NTOK);
    k_tohalf<<<(int)(NLAT / 4 / 256), 256>>>(latents, latH, NLAT);
    k_prep_w<<<(DIM * KIN + 255) / 256, 256>>>(conv_w, wcH);
    k_prep_wr<<<(DIM * DIM + 255) / 256, 256>>>(W_lat, W_tok, W_vlat, W_vtok, wrH);

    // conv as GEMM: tok (f32 exact +bias) + tokH (half)
    k_gemm_h<2><<<dim3(DIM / BN, (NB * SSEQ) / BM, 1), 128, SM_BYTES>>>(
        toksH, wcH, tok, nullptr, tokH, KIN, KIN, KIN, DIM, 0, 0, 0, 0,
        1.f, conv_b, nullptr, 0);

    // projections -> half
    k_gemm_h<3><<<dim3(DIM / BN, (NB * LSEQ) / BM, 1), 128, SM_BYTES>>>(
        latH, wrH + 0 * DIM * DIM, nullptr, nullptr, rlatH, DIM, DIM, DIM, DIM, 0, 0, 0, 0,
        1.f, nullptr, nullptr, 0);
    k_gemm_h<3><<<dim3(DIM / BN, (NB * LSEQ) / BM, 1), 128, SM_BYTES>>>(
        latH, wrH + 2 * DIM * DIM, nullptr, nullptr, vlatH, DIM, DIM, DIM, DIM, 0, 0, 0, 0,
        1.f, nullptr, nullptr, 0);
    k_gemm_h<3><<<dim3(DIM / BN, (NB * SSEQ) / BM, 1), 128, SM_BYTES>>>(
        tokH, wrH + 1 * DIM * DIM, nullptr, nullptr, rtokH, DIM, DIM, DIM, DIM, 0, 0, 0, 0,
        1.f, nullptr, nullptr, 0);
    k_gemm_h<3><<<dim3(DIM / BN, (NB * SSEQ) / BM, 1), 128, SM_BYTES>>>(
        tokH, wrH + 3 * DIM * DIM, nullptr, nullptr, vtokH, DIM, DIM, DIM, DIM, 0, 0, 0, 0,
        1.f, nullptr, nullptr, 0);

    // V transposes (half): (seq, E) -> (E, seq)
    k_transpose_h<<<dim3(DIM / 32, LSEQ / 32, NB), 256>>>(vlatH, vlatT, LSEQ, DIM);
    k_transpose_h<<<dim3(DIM / 32, SSEQ / 32, NB), 256>>>(vtokH, vtokT, SSEQ, DIM);

    // scores: A = Rlat @ Rtok^T / sqrt(512)  -> f32
    const float scale = 0.044194173824159216f;
    k_gemm_h<0><<<dim3(SSEQ / BN, LSEQ / BM, NB), 128, SM_BYTES>>>(
        rlatH, rtokH, smat, nullptr, nullptr, DIM, DIM, DIM, SSEQ,
        (long long)LSEQ * DIM, (long long)SSEQ * DIM, (long long)LSEQ * SSEQ, 0,
        scale, nullptr, nullptr, 0);

    // softmax stats + apply
    k_row_stats<<<NB * LSEQ, 256>>>(smat, rmax, rinv);
    k_col_part<<<dim3(SSEQ / 256, 8, NB), 256>>>(smat, pmax, psum);
    k_col_comb<<<dim3(SSEQ / 256, NB), 256>>>(pmax, psum, cmax, cinv);
    k_softmax_apply<<<dim3(SSEQ / 32, LSEQ / 32, NB), 256>>>(
        smat, prH, pcTH, rmax, rinv, cmax, cinv);

    // delta_lat = Prow @ VtokT^T + latents
    k_gemm_h<1><<<dim3(DIM / BN, LSEQ / BM, NB), 128, SM_BYTES>>>(
        prH, vtokT, out, out + CONCAT, nullptr, SSEQ, SSEQ, SSEQ, DIM,
        (long long)LSEQ * SSEQ, (long long)DIM * SSEQ,
        (long long)LSEQ * DIM, (long long)(LSEQ + SSEQ) * DIM,
        1.f, nullptr, latents, (long long)LSEQ * DIM);

    // delta_tok = PcT @ VlatT^T + tok
    k_gemm_h<1><<<dim3(DIM / BN, SSEQ / BM, NB), 128, SM_BYTES>>>(
        pcTH, vlatT, out + UL, out + CONCAT + (long long)LSEQ * DIM, nullptr, LSEQ, LSEQ, LSEQ, DIM,
        (long long)SSEQ * LSEQ, (long long)DIM * LSEQ,
        (long long)SSEQ * DIM, (long long)(LSEQ + SSEQ) * DIM,
        1.f, nullptr, tok, (long long)SSEQ * DIM);
}

// round 8
// speedup vs baseline: 1.9000x; 1.1139x over previous
#include <cuda_runtime.h>
#include <cuda_fp16.h>
#include <math.h>
#include <stdint.h>

// ---------------- problem constants ----------------
#define NB   8
#define LSEQ 1024
#define SSEQ 2048
#define DIM  512
#define TOKD 256
#define KIN  1280
#define TOKS 10240

// ---------------- scratch ----------------
__device__ __align__(256) __half g_WcH  [DIM * KIN];
__device__ __align__(256) __half g_WrH  [4 * DIM * DIM];
__device__ __align__(256) __half g_toksH[NB * TOKS * TOKD];
__device__ __align__(256) __half g_latH [NB * LSEQ * DIM];
__device__ __align__(256) float  g_tok  [NB * SSEQ * DIM];   // conv out exact (residual)
__device__ __align__(256) __half g_tokH [NB * SSEQ * DIM];
__device__ __align__(256) __half g_RlatH[NB * LSEQ * DIM];
__device__ __align__(256) __half g_RtokH[NB * SSEQ * DIM];
__device__ __align__(256) __half g_VlatH[NB * LSEQ * DIM];
__device__ __align__(256) __half g_VtokH[NB * SSEQ * DIM];
__device__ __align__(256) __half g_VlatT[NB * DIM * LSEQ];   // (E, L)
__device__ __align__(256) __half g_VtokT[NB * DIM * SSEQ];   // (E, S)
__device__ __align__(256) float  g_S    [NB * LSEQ * SSEQ];  // scores f32
__device__ __align__(256) __half g_PrH  [NB * LSEQ * SSEQ];  // row-softmax (L,S)
__device__ __align__(256) __half g_PcTH [NB * SSEQ * LSEQ];  // col-softmax^T (S,L)
__device__ __align__(256) float  g_rmax [NB * LSEQ];
__device__ __align__(256) float  g_rinv [NB * LSEQ];
__device__ __align__(256) float  g_cmax [NB * SSEQ];
__device__ __align__(256) float  g_cinv [NB * SSEQ];
__device__ __align__(256) float  g_pmax [NB * 8 * SSEQ];
__device__ __align__(256) float  g_psum [NB * 8 * SSEQ];

// ---------------- GEMM config: 128x128 block, 4 warps (64x64), fp16 k16 MMA + ldmatrix ----------------
#define BM 128
#define BN 128
#define BK 32
#define PH 40                       // halves per smem row
#define STAGES 3
#define ASZH (BM * PH)
#define BSZH (BN * PH)
#define SM_BYTES (STAGES * (ASZH + BSZH) * 2)   // 61440

__device__ __forceinline__ void mma_f16(float c[4], const uint32_t a[4], const uint32_t b[2]) {
    asm volatile(
        "mma.sync.aligned.m16n8k16.row.col.f32.f16.f16.f32 "
        "{%0,%1,%2,%3}, {%4,%5,%6,%7}, {%8,%9}, {%0,%1,%2,%3};"
        : "+f"(c[0]), "+f"(c[1]), "+f"(c[2]), "+f"(c[3])
        : "r"(a[0]), "r"(a[1]), "r"(a[2]), "r"(a[3]), "r"(b[0]), "r"(b[1]));
}

__device__ __forceinline__ void ldsm_x4(uint32_t r[4], uint32_t addr) {
    asm volatile("ldmatrix.sync.aligned.m8n8.x4.shared.b16 {%0,%1,%2,%3}, [%4];"
                 : "=r"(r[0]), "=r"(r[1]), "=r"(r[2]), "=r"(r[3]) : "r"(addr));
}

__device__ __forceinline__ void cpasync16(uint32_t dst, const void* src) {
    asm volatile("cp.async.cg.shared.global [%0], [%1], 16;" :: "r"(dst), "l"(src));
}

// ---------------- fp16 GEMM: acc(M,N) = A(M,K) @ B(N,K)^T, fp32 accumulate ----------------
// EPI=0: Cf = alpha*acc
// EPI=1: v = acc + addend; store Cf and Cf2
// EPI=2: Cf = acc + bias; Ch = half(Cf)
// EPI=3: Ch = half(acc)
template<int EPI>
__global__ __launch_bounds__(128, 2) void k_gemm_h(
    const __half* __restrict__ A, const __half* __restrict__ B,
    float* __restrict__ Cf, float* __restrict__ Cf2, __half* __restrict__ Ch,
    int K, int lda, int ldb, int ldc,
    long long sA, long long sB, long long sC, long long sC2,
    float alpha, const float* __restrict__ bias,
    const float* __restrict__ addend, long long sAdd)
{
    extern __shared__ __half smh[];
    const uint32_t sbase = (uint32_t)__cvta_generic_to_shared(smh);
    const uint32_t aReg = sbase;                        // STAGES*ASZH halves
    const uint32_t bReg = sbase + STAGES * ASZH * 2;    // STAGES*BSZH halves

    const long long z = blockIdx.z;
    A += z * sA;
    B += z * sB;
    if (EPI == 0 || EPI == 1 || EPI == 2) Cf += z * sC;
    if (EPI == 1) { Cf2 += z * sC2; addend += z * sAdd; }
    if (EPI == 2 || EPI == 3) Ch += z * sC;

    const int m0 = blockIdx.y * BM, n0 = blockIdx.x * BN;
    const int tid = threadIdx.x;
    const int wid = tid >> 5, lane = tid & 31;
    const int grp = lane >> 2, tig = lane & 3;
    const int wm = (wid >> 1) * 64, wn = (wid & 1) * 64;

    // ldmatrix per-lane base addresses (buf 0, ks 0), in bytes
    // A mi: matrix index = lane>>3: {m+r/c0, m+8+r/c0, m+r/c1, m+8+r/c1}
    uint32_t aAddr[4], bAddr[4];
    {
        const int r = lane & 7;
        const int aRowOff = ((lane >> 3) & 1) * 8 + r;     // +8 for matrices 1,3
        const int aChunk = lane >> 4;                      // matrices 2,3 -> chunk 1
#pragma unroll
        for (int mi = 0; mi < 4; mi++)
            aAddr[mi] = aReg + (uint32_t)((wm + mi * 16 + aRowOff) * PH + aChunk * 8) * 2;
        // B pair p covers ni=2p,2p+1: matrices {row(2p)+r/c0, row(2p)+r/c1, row(2p+1)+r/c0, row(2p+1)+r/c1}
        const int bRow = (lane >> 4);                      // which ni of the pair
        const int bChunk = (lane >> 3) & 1;
#pragma unroll
        for (int p = 0; p < 4; p++)
            bAddr[p] = bReg + (uint32_t)((wn + (2 * p + bRow) * 8 + r) * PH + bChunk * 8) * 2;
    }

    float acc[4][8][4];
#pragma unroll
    for (int i = 0; i < 4; i++)
#pragma unroll
        for (int j = 0; j < 8; j++)
#pragma unroll
            for (int r = 0; r < 4; r++) acc[i][j][r] = 0.f;

    auto loadTile = [&](int t, int buf) {
        const int k0 = t * BK;
        const uint32_t Ab = aReg + buf * ASZH * 2;
        const uint32_t Bb = bReg + buf * BSZH * 2;
#pragma unroll
        for (int i = 0; i < 4; i++) {
            int idx = i * 128 + tid;
            int row = idx >> 2, seg = idx & 3;
            cpasync16(Ab + (uint32_t)(row * PH + seg * 8) * 2,
                      A + (long long)(m0 + row) * lda + k0 + seg * 8);
        }
#pragma unroll
        for (int i = 0; i < 4; i++) {
            int idx = i * 128 + tid;
            int row = idx >> 2, seg = idx & 3;
            cpasync16(Bb + (uint32_t)(row * PH + seg * 8) * 2,
                      B + (long long)(n0 + row) * ldb + k0 + seg * 8);
        }
        asm volatile("cp.async.commit_group;");
    };

    auto compute = [&](int buf) {
        const uint32_t aOff = buf * ASZH * 2;
        const uint32_t bOff = buf * BSZH * 2;
#pragma unroll
        for (int ks = 0; ks < 2; ks++) {
            uint32_t af[4][4], bf[8][2];
#pragma unroll
            for (int mi = 0; mi < 4; mi++)
                ldsm_x4(af[mi], aAddr[mi] + aOff + ks * 32);
#pragma unroll
            for (int p = 0; p < 4; p++) {
                uint32_t t4[4];
                ldsm_x4(t4, bAddr[p] + bOff + ks * 32);
                bf[2 * p][0] = t4[0]; bf[2 * p][1] = t4[1];
                bf[2 * p + 1][0] = t4[2]; bf[2 * p + 1][1] = t4[3];
            }
#pragma unroll
            for (int mi = 0; mi < 4; mi++)
#pragma unroll
                for (int ni = 0; ni < 8; ni++)
                    mma_f16(acc[mi][ni], af[mi], bf[ni]);
        }
    };

    const int tiles = K / BK;
#pragma unroll
    for (int s = 0; s < STAGES - 1; s++) loadTile(s, s);
    for (int t = 0; t < tiles; t++) {
        asm volatile("cp.async.wait_group %0;" :: "n"(STAGES - 2));
        __syncthreads();
        if (t + STAGES - 1 < tiles) loadTile(t + STAGES - 1, (t + STAGES - 1) % STAGES);
        compute(t % STAGES);
    }

    // epilogue
#pragma unroll
    for (int mi = 0; mi < 4; mi++) {
        const int r = m0 + wm + mi * 16 + grp;
#pragma unroll
        for (int ni = 0; ni < 8; ni++) {
            const int c = n0 + wn + ni * 8 + tig * 2;
            float2 v0 = {acc[mi][ni][0], acc[mi][ni][1]};
            float2 v1 = {acc[mi][ni][2], acc[mi][ni][3]};
            if (EPI == 0) {
                v0.x *= alpha; v0.y *= alpha; v1.x *= alpha; v1.y *= alpha;
                *(float2*)(Cf + (long long)r * ldc + c) = v0;
                *(float2*)(Cf + (long long)(r + 8) * ldc + c) = v1;
            } else if (EPI == 3) {
                *(__half2*)(Ch + (long long)r * ldc + c) = __floats2half2_rn(v0.x, v0.y);
                *(__half2*)(Ch + (long long)(r + 8) * ldc + c) = __floats2half2_rn(v1.x, v1.y);
            } else if (EPI == 2) {
                float bx = bias[c], by = bias[c + 1];
                v0.x += bx; v0.y += by; v1.x += bx; v1.y += by;
                *(float2*)(Cf + (long long)r * ldc + c) = v0;
                *(float2*)(Cf + (long long)(r + 8) * ldc + c) = v1;
                *(__half2*)(Ch + (long long)r * ldc + c) = __floats2half2_rn(v0.x, v0.y);
                *(__half2*)(Ch + (long long)(r + 8) * ldc + c) = __floats2half2_rn(v1.x, v1.y);
            } else {   // EPI == 1
                float2 a0 = *(const float2*)(addend + (long long)r * ldc + c);
                float2 a1 = *(const float2*)(addend + (long long)(r + 8) * ldc + c);
                v0.x += a0.x; v0.y += a0.y;
                v1.x += a1.x; v1.y += a1.y;
                *(float2*)(Cf  + (long long)r * ldc + c) = v0;
                *(float2*)(Cf  + (long long)(r + 8) * ldc + c) = v1;
                *(float2*)(Cf2 + (long long)r * ldc + c) = v0;
                *(float2*)(Cf2 + (long long)(r + 8) * ldc + c) = v1;
            }
        }
    }
}

// ---------------- prep kernels ----------------
__global__ void k_prep_w(const float* __restrict__ w, __half* __restrict__ wc) {
    int i = blockIdx.x * 256 + threadIdx.x;
    if (i < DIM * KIN) {
        int e = i / KIN;
        int r = i - e * KIN;
        int t = r / TOKD;
        int c = r - t * TOKD;
        wc[i] = __float2half_rn(w[e * KIN + c * 5 + t]);
    }
}
__global__ void k_prep_wr(const float* __restrict__ w0, const float* __restrict__ w1,
                          const float* __restrict__ w2, const float* __restrict__ w3,
                          __half* __restrict__ out) {
    int i = blockIdx.x * 256 + threadIdx.x;
    if (i < DIM * DIM) {
        out[i]                 = __float2half_rn(w0[i]);
        out[i + DIM * DIM]     = __float2half_rn(w1[i]);
        out[i + 2 * DIM * DIM] = __float2half_rn(w2[i]);
        out[i + 3 * DIM * DIM] = __float2half_rn(w3[i]);
    }
}
__global__ void k_tohalf(const float* __restrict__ s, __half* __restrict__ d, long long n) {
    long long i = ((long long)blockIdx.x * 256 + threadIdx.x) * 4;
    if (i < n) {
        float4 v = *(const float4*)(s + i);
        *(__half2*)(d + i)     = __floats2half2_rn(v.x, v.y);
        *(__half2*)(d + i + 2) = __floats2half2_rn(v.z, v.w);
    }
}

// transpose per batch (half): src (R,C) -> dst (C,R)
__global__ __launch_bounds__(256) void k_transpose_h(const __half* __restrict__ src,
                                                     __half* __restrict__ dst, int R, int C) {
    __shared__ __half tile[32][34];
    const int b = blockIdx.z;
    src += (long long)b * R * C;
    dst += (long long)b * R * C;
    const int c0 = blockIdx.x * 32, r0 = blockIdx.y * 32;
    const int tx = threadIdx.x & 31, ty = threadIdx.x >> 5;
#pragma unroll
    for (int i = 0; i < 4; i++)
        tile[ty + i * 8][tx] = src[(long long)(r0 + ty + i * 8) * C + c0 + tx];
    __syncthreads();
#pragma unroll
    for (int i = 0; i < 4; i++)
        dst[(long long)(c0 + ty + i * 8) * R + r0 + tx] = tile[tx][ty + i * 8];
}

// ---------------- softmax stats ----------------
__global__ void k_row_stats(const float* __restrict__ A,
                            float* __restrict__ rmax, float* __restrict__ rinv) {
    __shared__ float red[256];
    long long r = blockIdx.x;
    const float* row = A + r * SSEQ;
    int tid = threadIdx.x;
    float m = -1e30f;
    for (int c = tid; c < SSEQ; c += 256) m = fmaxf(m, row[c]);
    red[tid] = m; __syncthreads();
    for (int s = 128; s > 0; s >>= 1) {
        if (tid < s) red[tid] = fmaxf(red[tid], red[tid + s]);
        __syncthreads();
    }
    m = red[0];
    __syncthreads();
    float sum = 0.f;
    for (int c = tid; c < SSEQ; c += 256) sum += __expf(row[c] - m);
    red[tid] = sum; __syncthreads();
    for (int s = 128; s > 0; s >>= 1) {
        if (tid < s) red[tid] += red[tid + s];
        __syncthreads();
    }
    if (tid == 0) { rmax[r] = m; rinv[r] = 1.f / red[0]; }
}

__global__ void k_col_part(const float* __restrict__ A,
                           float* __restrict__ pmax, float* __restrict__ psum) {
    const int b = blockIdx.z, ch = blockIdx.y;
    const int s = blockIdx.x * 256 + threadIdx.x;
    const float* Ab = A + (long long)b * LSEQ * SSEQ + (long long)ch * 128 * SSEQ + s;
    float m = -1e30f, sum = 0.f;
#pragma unroll 4
    for (int l = 0; l < 128; l++) {
        float v = Ab[(long long)l * SSEQ];
        float mn = fmaxf(m, v);
        sum = sum * __expf(m - mn) + __expf(v - mn);
        m = mn;
    }
    pmax[(b * 8 + ch) * SSEQ + s] = m;
    psum[(b * 8 + ch) * SSEQ + s] = sum;
}
__global__ void k_col_comb(const float* __restrict__ pmax, const float* __restrict__ psum,
                           float* __restrict__ cmax, float* __restrict__ cinv) {
    const int b = blockIdx.y;
    const int s = blockIdx.x * 256 + threadIdx.x;
    float m = -1e30f;
#pragma unroll
    for (int c = 0; c < 8; c++) m = fmaxf(m, pmax[(b * 8 + c) * SSEQ + s]);
    float sum = 0.f;
#pragma unroll
    for (int c = 0; c < 8; c++)
        sum += psum[(b * 8 + c) * SSEQ + s] * __expf(pmax[(b * 8 + c) * SSEQ + s] - m);
    cmax[b * SSEQ + s] = m;
    cinv[b * SSEQ + s] = 1.f / sum;
}

// ---------------- apply both softmaxes -> half ----------------
__global__ __launch_bounds__(256) void k_softmax_apply(
    const float* __restrict__ A, __half* __restrict__ Pr, __half* __restrict__ PcT,
    const float* __restrict__ rmax, const float* __restrict__ rinv,
    const float* __restrict__ cmax, const float* __restrict__ cinv)
{
    __shared__ float tile[32][33];
    const int b = blockIdx.z;
    const int s0 = blockIdx.x * 32, l0 = blockIdx.y * 32;
    const float* Ab = A + (long long)b * LSEQ * SSEQ;
    __half* Prb = Pr + (long long)b * LSEQ * SSEQ;
    __half* Pcb = PcT + (long long)b * SSEQ * LSEQ;
    const int tx = threadIdx.x & 31, ty = threadIdx.x >> 5;

    const float cm = cmax[b * SSEQ + s0 + tx];
    const float ci = cinv[b * SSEQ + s0 + tx];
#pragma unroll
    for (int i = 0; i < 4; i++) {
        const int l = l0 + ty + i * 8;
        float v = Ab[(long long)l * SSEQ + s0 + tx];
        Prb[(long long)l * SSEQ + s0 + tx] =
            __float2half_rn(__expf(v - rmax[b * LSEQ + l]) * rinv[b * LSEQ + l]);
        tile[ty + i * 8][tx] = __expf(v - cm) * ci;
    }
    __syncthreads();
#pragma unroll
    for (int i = 0; i < 4; i++) {
        const int s = s0 + ty + i * 8;
        Pcb[(long long)s * LSEQ + l0 + tx] = __float2half_rn(tile[tx][ty + i * 8]);
    }
}

// ---------------- launch ----------------
extern "C" void kernel_launch(void* const* d_in, const int* in_sizes, int n_in,
                              void* d_out, int out_size) {
    const float* latents = (const float*)d_in[0];
    const float* tokens  = (const float*)d_in[1];
    const float* W_lat   = (const float*)d_in[2];
    const float* W_tok   = (const float*)d_in[3];
    const float* W_vlat  = (const float*)d_in[4];
    const float* W_vtok  = (const float*)d_in[5];
    const float* conv_w  = (const float*)d_in[6];
    const float* conv_b  = (const float*)d_in[7];
    float* out = (float*)d_out;

    __half *wcH, *wrH, *toksH, *latH, *tokH, *rlatH, *rtokH, *vlatH, *vtokH, *vlatT, *vtokT, *prH, *pcTH;
    float *tok, *smat, *rmax, *rinv, *cmax, *cinv, *pmax, *psum;
    cudaGetSymbolAddress((void**)&wcH,   g_WcH);
    cudaGetSymbolAddress((void**)&wrH,   g_WrH);
    cudaGetSymbolAddress((void**)&toksH, g_toksH);
    cudaGetSymbolAddress((void**)&latH,  g_latH);
    cudaGetSymbolAddress((void**)&tok,   g_tok);
    cudaGetSymbolAddress((void**)&tokH,  g_tokH);
    cudaGetSymbolAddress((void**)&rlatH, g_RlatH);
    cudaGetSymbolAddress((void**)&rtokH, g_RtokH);
    cudaGetSymbolAddress((void**)&vlatH, g_VlatH);
    cudaGetSymbolAddress((void**)&vtokH, g_VtokH);
    cudaGetSymbolAddress((void**)&vlatT, g_VlatT);
    cudaGetSymbolAddress((void**)&vtokT, g_VtokT);
    cudaGetSymbolAddress((void**)&prH,   g_PrH);
    cudaGetSymbolAddress((void**)&pcTH,  g_PcTH);
    cudaGetSymbolAddress((void**)&smat,  g_S);
    cudaGetSymbolAddress((void**)&rmax,  g_rmax);
    cudaGetSymbolAddress((void**)&rinv,  g_rinv);
    cudaGetSymbolAddress((void**)&cmax,  g_cmax);
    cudaGetSymbolAddress((void**)&cinv,  g_cinv);
    cudaGetSymbolAddress((void**)&pmax,  g_pmax);
    cudaGetSymbolAddress((void**)&psum,  g_psum);

    cudaFuncSetAttribute(k_gemm_h<0>, cudaFuncAttributeMaxDynamicSharedMemorySize, SM_BYTES);
    cudaFuncSetAttribute(k_gemm_h<1>, cudaFuncAttributeMaxDynamicSharedMemorySize, SM_BYTES);
    cudaFuncSetAttribute(k_gemm_h<2>, cudaFuncAttributeMaxDynamicSharedMemorySize, SM_BYTES);
    cudaFuncSetAttribute(k_gemm_h<3>, cudaFuncAttributeMaxDynamicSharedMemorySize, SM_BYTES);

    const long long UL = (long long)NB * LSEQ * DIM;
    const long long UT = (long long)NB * SSEQ * DIM;
    const long long CONCAT = UL + UT;

    // inputs -> half
    const long long NTOK = (long long)NB * TOKS * TOKD;
    const long long NLAT = (long long)NB * LSEQ * DIM;
    k_tohalf<<<(int)(NTOK / 4 / 256), 256>>>(tokens, toksH, NTOK);
    k_tohalf<<<(int)(NLAT / 4 / 256), 256>>>(latents, latH, NLAT);
    k_prep_w<<<(DIM * KIN + 255) / 256, 256>>>(conv_w, wcH);
    k_prep_wr<<<(DIM * DIM + 255) / 256, 256>>>(W_lat, W_tok, W_vlat, W_vtok, wrH);

    // conv as GEMM: tok (f32 exact +bias) + tokH (half)
    k_gemm_h<2><<<dim3(DIM / BN, (NB * SSEQ) / BM, 1), 128, SM_BYTES>>>(
        toksH, wcH, tok, nullptr, tokH, KIN, KIN, KIN, DIM, 0, 0, 0, 0,
        1.f, conv_b, nullptr, 0);

    // projections -> half
    k_gemm_h<3><<<dim3(DIM / BN, (NB * LSEQ) / BM, 1), 128, SM_BYTES>>>(
        latH, wrH + 0 * DIM * DIM, nullptr, nullptr, rlatH, DIM, DIM, DIM, DIM, 0, 0, 0, 0,
        1.f, nullptr, nullptr, 0);
    k_gemm_h<3><<<dim3(DIM / BN, (NB * LSEQ) / BM, 1), 128, SM_BYTES>>>(
        latH, wrH + 2 * DIM * DIM, nullptr, nullptr, vlatH, DIM, DIM, DIM, DIM, 0, 0, 0, 0,
        1.f, nullptr, nullptr, 0);
    k_gemm_h<3><<<dim3(DIM / BN, (NB * SSEQ) / BM, 1), 128, SM_BYTES>>>(
        tokH, wrH + 1 * DIM * DIM, nullptr, nullptr, rtokH, DIM, DIM, DIM, DIM, 0, 0, 0, 0,
        1.f, nullptr, nullptr, 0);
    k_gemm_h<3><<<dim3(DIM / BN, (NB * SSEQ) / BM, 1), 128, SM_BYTES>>>(
        tokH, wrH + 3 * DIM * DIM, nullptr, nullptr, vtokH, DIM, DIM, DIM, DIM, 0, 0, 0, 0,
        1.f, nullptr, nullptr, 0);

    // V transposes (half): (seq, E) -> (E, seq)
    k_transpose_h<<<dim3(DIM / 32, LSEQ / 32, NB), 256>>>(vlatH, vlatT, LSEQ, DIM);
    k_transpose_h<<<dim3(DIM / 32, SSEQ / 32, NB), 256>>>(vtokH, vtokT, SSEQ, DIM);

    // scores: A = Rlat @ Rtok^T / sqrt(512)  -> f32
    const float scale = 0.044194173824159216f;
    k_gemm_h<0><<<dim3(SSEQ / BN, LSEQ / BM, NB), 128, SM_BYTES>>>(
        rlatH, rtokH, smat, nullptr, nullptr, DIM, DIM, DIM, SSEQ,
        (long long)LSEQ * DIM, (long long)SSEQ * DIM, (long long)LSEQ * SSEQ, 0,
        scale, nullptr, nullptr, 0);

    // softmax stats + apply
    k_row_stats<<<NB * LSEQ, 256>>>(smat, rmax, rinv);
    k_col_part<<<dim3(SSEQ / 256, 8, NB), 256>>>(smat, pmax, psum);
    k_col_comb<<<dim3(SSEQ / 256, NB), 256>>>(pmax, psum, cmax, cinv);
    k_softmax_apply<<<dim3(SSEQ / 32, LSEQ / 32, NB), 256>>>(
        smat, prH, pcTH, rmax, rinv, cmax, cinv);

    // delta_lat = Prow @ VtokT^T + latents
    k_gemm_h<1><<<dim3(DIM / BN, LSEQ / BM, NB), 128, SM_BYTES>>>(
        prH, vtokT, out, out + CONCAT, nullptr, SSEQ, SSEQ, SSEQ, DIM,
        (long long)LSEQ * SSEQ, (long long)DIM * SSEQ,
        (long long)LSEQ * DIM, (long long)(LSEQ + SSEQ) * DIM,
        1.f, nullptr, latents, (long long)LSEQ * DIM);

    // delta_tok = PcT @ VlatT^T + tok
    k_gemm_h<1><<<dim3(DIM / BN, SSEQ / BM, NB), 128, SM_BYTES>>>(
        pcTH, vlatT, out + UL, out + CONCAT + (long long)LSEQ * DIM, nullptr, LSEQ, LSEQ, LSEQ, DIM,
        (long long)SSEQ * LSEQ, (long long)DIM * LSEQ,
        (long long)SSEQ * DIM, (long long)(LSEQ + SSEQ) * DIM,
        1.f, nullptr, tok, (long long)SSEQ * DIM);
}

// round 9
// speedup vs baseline: 2.0157x; 1.0609x over previous
#include <cuda_runtime.h>
#include <cuda_fp16.h>
#include <math.h>
#include <stdint.h>

// ---------------- problem constants ----------------
#define NB   8
#define LSEQ 1024
#define SSEQ 2048
#define DIM  512
#define TOKD 256
#define KIN  1280
#define TOKS 10240

// ---------------- scratch ----------------
__device__ __align__(256) __half g_WcH  [DIM * KIN];
__device__ __align__(256) __half g_WrH  [4 * DIM * DIM];
__device__ __align__(256) __half g_toksH[NB * TOKS * TOKD];
__device__ __align__(256) __half g_latH [NB * LSEQ * DIM];
__device__ __align__(256) float  g_tok  [NB * SSEQ * DIM];
__device__ __align__(256) __half g_tokH [NB * SSEQ * DIM];
__device__ __align__(256) __half g_RlatH[NB * LSEQ * DIM];
__device__ __align__(256) __half g_RtokH[NB * SSEQ * DIM];
__device__ __align__(256) __half g_VlatH[NB * LSEQ * DIM];
__device__ __align__(256) __half g_VtokH[NB * SSEQ * DIM];
__device__ __align__(256) __half g_VlatT[NB * DIM * LSEQ];
__device__ __align__(256) __half g_VtokT[NB * DIM * SSEQ];
__device__ __align__(256) float  g_S    [NB * LSEQ * SSEQ];
__device__ __align__(256) __half g_PrH  [NB * LSEQ * SSEQ];
__device__ __align__(256) __half g_PcTH [NB * SSEQ * LSEQ];
__device__ __align__(256) float  g_rmax [NB * LSEQ];
__device__ __align__(256) float  g_rinv [NB * LSEQ];
__device__ __align__(256) float  g_cmax [NB * SSEQ];
__device__ __align__(256) float  g_cinv [NB * SSEQ];
// tile partial stats from scores GEMM: rows: 16 x-tiles; cols: 8 y-tiles
__device__ __align__(256) float  g_prm  [NB * 16 * LSEQ];
__device__ __align__(256) float  g_prs  [NB * 16 * LSEQ];
__device__ __align__(256) float  g_pcm  [NB * 8 * SSEQ];
__device__ __align__(256) float  g_pcs  [NB * 8 * SSEQ];

// ---------------- GEMM config ----------------
#define BM 128
#define BN 128
#define BK 32
#define PH 40
#define STAGES 3
#define ASZH (BM * PH)
#define BSZH (BN * PH)
#define SM_BYTES (STAGES * (ASZH + BSZH) * 2)   // 61440

__device__ __forceinline__ void mma_f16(float c[4], const uint32_t a[4], const uint32_t b[2]) {
    asm volatile(
        "mma.sync.aligned.m16n8k16.row.col.f32.f16.f16.f32 "
        "{%0,%1,%2,%3}, {%4,%5,%6,%7}, {%8,%9}, {%0,%1,%2,%3};"
        : "+f"(c[0]), "+f"(c[1]), "+f"(c[2]), "+f"(c[3])
        : "r"(a[0]), "r"(a[1]), "r"(a[2]), "r"(a[3]), "r"(b[0]), "r"(b[1]));
}

__device__ __forceinline__ void ldsm_x4(uint32_t r[4], uint32_t addr) {
    asm volatile("ldmatrix.sync.aligned.m8n8.x4.shared.b16 {%0,%1,%2,%3}, [%4];"
                 : "=r"(r[0]), "=r"(r[1]), "=r"(r[2]), "=r"(r[3]) : "r"(addr));
}

__device__ __forceinline__ void cpasync16(uint32_t dst, const void* src) {
    asm volatile("cp.async.cg.shared.global [%0], [%1], 16;" :: "r"(dst), "l"(src));
}

// online-softmax pair merge: (m,s) <- (m,s) (+) (om,os)
__device__ __forceinline__ void msmerge(float& m, float& s, float om, float os) {
    float M = fmaxf(m, om);
    s = s * __expf(m - M) + os * __expf(om - M);
    m = M;
}

// ---------------- fp16 GEMM: acc(M,N) = A(M,K) @ B(N,K)^T, fp32 accumulate ----------------
// EPI=0: Cf = alpha*acc
// EPI=1: v = acc + addend; store Cf and Cf2
// EPI=2: Cf = acc + bias; Ch = half(Cf)
// EPI=3: Ch = half(acc)
// EPI=4: Cf = alpha*acc; also emit tile-partial row/col softmax stats
template<int EPI>
__global__ __launch_bounds__(128, 2) void k_gemm_h(
    const __half* __restrict__ A, const __half* __restrict__ B,
    float* __restrict__ Cf, float* __restrict__ Cf2, __half* __restrict__ Ch,
    int K, int lda, int ldb, int ldc,
    long long sA, long long sB, long long sC, long long sC2,
    float alpha, const float* __restrict__ bias,
    const float* __restrict__ addend, long long sAdd,
    float* __restrict__ prm, float* __restrict__ prs,
    float* __restrict__ pcm, float* __restrict__ pcs)
{
    extern __shared__ __half smh[];
    const uint32_t sbase = (uint32_t)__cvta_generic_to_shared(smh);
    const uint32_t aReg = sbase;
    const uint32_t bReg = sbase + STAGES * ASZH * 2;

    const long long z = blockIdx.z;
    A += z * sA;
    B += z * sB;
    if (EPI == 0 || EPI == 1 || EPI == 2 || EPI == 4) Cf += z * sC;
    if (EPI == 1) { Cf2 += z * sC2; addend += z * sAdd; }
    if (EPI == 2 || EPI == 3) Ch += z * sC;

    const int m0 = blockIdx.y * BM, n0 = blockIdx.x * BN;
    const int tid = threadIdx.x;
    const int wid = tid >> 5, lane = tid & 31;
    const int grp = lane >> 2, tig = lane & 3;
    const int wm = (wid >> 1) * 64, wn = (wid & 1) * 64;

    uint32_t aAddr[4], bAddr[4];
    {
        const int r = lane & 7;
        const int aRowOff = ((lane >> 3) & 1) * 8 + r;
        const int aChunk = lane >> 4;
#pragma unroll
        for (int mi = 0; mi < 4; mi++)
            aAddr[mi] = aReg + (uint32_t)((wm + mi * 16 + aRowOff) * PH + aChunk * 8) * 2;
        const int bRow = (lane >> 4);
        const int bChunk = (lane >> 3) & 1;
#pragma unroll
        for (int p = 0; p < 4; p++)
            bAddr[p] = bReg + (uint32_t)((wn + (2 * p + bRow) * 8 + r) * PH + bChunk * 8) * 2;
    }

    float acc[4][8][4];
#pragma unroll
    for (int i = 0; i < 4; i++)
#pragma unroll
        for (int j = 0; j < 8; j++)
#pragma unroll
            for (int r = 0; r < 4; r++) acc[i][j][r] = 0.f;

    auto loadTile = [&](int t, int buf) {
        const int k0 = t * BK;
        const uint32_t Ab = aReg + buf * ASZH * 2;
        const uint32_t Bb = bReg + buf * BSZH * 2;
#pragma unroll
        for (int i = 0; i < 4; i++) {
            int idx = i * 128 + tid;
            int row = idx >> 2, seg = idx & 3;
            cpasync16(Ab + (uint32_t)(row * PH + seg * 8) * 2,
                      A + (long long)(m0 + row) * lda + k0 + seg * 8);
        }
#pragma unroll
        for (int i = 0; i < 4; i++) {
            int idx = i * 128 + tid;
            int row = idx >> 2, seg = idx & 3;
            cpasync16(Bb + (uint32_t)(row * PH + seg * 8) * 2,
                      B + (long long)(n0 + row) * ldb + k0 + seg * 8);
        }
        asm volatile("cp.async.commit_group;");
    };

    auto compute = [&](int buf) {
        const uint32_t aOff = buf * ASZH * 2;
        const uint32_t bOff = buf * BSZH * 2;
#pragma unroll
        for (int ks = 0; ks < 2; ks++) {
            uint32_t af[4][4], bf[8][2];
#pragma unroll
            for (int mi = 0; mi < 4; mi++)
                ldsm_x4(af[mi], aAddr[mi] + aOff + ks * 32);
#pragma unroll
            for (int p = 0; p < 4; p++) {
                uint32_t t4[4];
                ldsm_x4(t4, bAddr[p] + bOff + ks * 32);
                bf[2 * p][0] = t4[0]; bf[2 * p][1] = t4[1];
                bf[2 * p + 1][0] = t4[2]; bf[2 * p + 1][1] = t4[3];
            }
#pragma unroll
            for (int mi = 0; mi < 4; mi++)
#pragma unroll
                for (int ni = 0; ni < 8; ni++)
                    mma_f16(acc[mi][ni], af[mi], bf[ni]);
        }
    };

    const int tiles = K / BK;
#pragma unroll
    for (int s = 0; s < STAGES - 1; s++) loadTile(s, s);
    for (int t = 0; t < tiles; t++) {
        asm volatile("cp.async.wait_group %0;" :: "n"(STAGES - 2));
        __syncthreads();
        if (t + STAGES - 1 < tiles) loadTile(t + STAGES - 1, (t + STAGES - 1) % STAGES);
        compute(t % STAGES);
    }

    if (EPI == 4) {
        // scale in place, store S, then tile-partial stats
#pragma unroll
        for (int mi = 0; mi < 4; mi++)
#pragma unroll
            for (int ni = 0; ni < 8; ni++)
#pragma unroll
                for (int r = 0; r < 4; r++) acc[mi][ni][r] *= alpha;
#pragma unroll
        for (int mi = 0; mi < 4; mi++) {
            const int r = m0 + wm + mi * 16 + grp;
#pragma unroll
            for (int ni = 0; ni < 8; ni++) {
                const int c = n0 + wn + ni * 8 + tig * 2;
                *(float2*)(Cf + (long long)r * ldc + c) = make_float2(acc[mi][ni][0], acc[mi][ni][1]);
                *(float2*)(Cf + (long long)(r + 8) * ldc + c) = make_float2(acc[mi][ni][2], acc[mi][ni][3]);
            }
        }
        float* smf = (float*)smh;    // reuse pipeline smem: [4 warps][64][2]
        __syncthreads();
        // ---- row partials (over this tile's 128 columns) ----
#pragma unroll
        for (int mi = 0; mi < 4; mi++) {
#pragma unroll
            for (int h = 0; h < 2; h++) {
                float m = -1e30f;
#pragma unroll
                for (int ni = 0; ni < 8; ni++) {
                    m = fmaxf(m, acc[mi][ni][2 * h]);
                    m = fmaxf(m, acc[mi][ni][2 * h + 1]);
                }
                float s = 0.f;
#pragma unroll
                for (int ni = 0; ni < 8; ni++) {
                    s += __expf(acc[mi][ni][2 * h] - m);
                    s += __expf(acc[mi][ni][2 * h + 1] - m);
                }
#pragma unroll
                for (int off = 1; off <= 2; off <<= 1) {
                    float om = __shfl_xor_sync(0xffffffffu, m, off);
                    float os = __shfl_xor_sync(0xffffffffu, s, off);
                    msmerge(m, s, om, os);
                }
                if (tig == 0) {
                    int lr = mi * 16 + grp + 8 * h;   // 0..63 within warp rows
                    smf[(wid * 64 + lr) * 2 + 0] = m;
                    smf[(wid * 64 + lr) * 2 + 1] = s;
                }
            }
        }
        __syncthreads();
        if (tid < 128) {
            const int r = tid;
            const int w0 = (r >> 6) * 2;     // rows 0-63: warps 0,1 ; 64-127: warps 2,3
            const int lr = r & 63;
            float m = smf[((w0) * 64 + lr) * 2 + 0];
            float s = smf[((w0) * 64 + lr) * 2 + 1];
            msmerge(m, s, smf[((w0 + 1) * 64 + lr) * 2 + 0], smf[((w0 + 1) * 64 + lr) * 2 + 1]);
            const long long idx = (z * 16 + blockIdx.x) * LSEQ + m0 + r;
            prm[idx] = m;
            prs[idx] = s;
        }
        __syncthreads();
        // ---- column partials (over this tile's 128 rows) ----
#pragma unroll
        for (int ni = 0; ni < 8; ni++) {
#pragma unroll
            for (int j = 0; j < 2; j++) {
                float m = -1e30f;
#pragma unroll
                for (int mi = 0; mi < 4; mi++) {
                    m = fmaxf(m, acc[mi][ni][j]);
                    m = fmaxf(m, acc[mi][ni][2 + j]);
                }
                float s = 0.f;
#pragma unroll
                for (int mi = 0; mi < 4; mi++) {
                    s += __expf(acc[mi][ni][j] - m);
                    s += __expf(acc[mi][ni][2 + j] - m);
                }
#pragma unroll
                for (int off = 4; off <= 16; off <<= 1) {
                    float om = __shfl_xor_sync(0xffffffffu, m, off);
                    float os = __shfl_xor_sync(0xffffffffu, s, off);
                    msmerge(m, s, om, os);
                }
                if (grp == 0) {
                    int lc = ni * 8 + tig * 2 + j;    // 0..63 within warp cols
                    smf[(wid * 64 + lc) * 2 + 0] = m;
                    smf[(wid * 64 + lc) * 2 + 1] = s;
                }
            }
        }
        __syncthreads();
        if (tid < 128) {
            const int c = tid;
            const int w0 = (c >> 6);         // cols 0-63: warps 0,2 ; 64-127: warps 1,3
            const int lc = c & 63;
            float m = smf[((w0) * 64 + lc) * 2 + 0];
            float s = smf[((w0) * 64 + lc) * 2 + 1];
            msmerge(m, s, smf[((w0 + 2) * 64 + lc) * 2 + 0], smf[((w0 + 2) * 64 + lc) * 2 + 1]);
            const long long idx = (z * 8 + blockIdx.y) * SSEQ + n0 + c;
            pcm[idx] = m;
            pcs[idx] = s;
        }
        return;
    }

    // standard epilogues
#pragma unroll
    for (int mi = 0; mi < 4; mi++) {
        const int r = m0 + wm + mi * 16 + grp;
#pragma unroll
        for (int ni = 0; ni < 8; ni++) {
            const int c = n0 + wn + ni * 8 + tig * 2;
            float2 v0 = {acc[mi][ni][0], acc[mi][ni][1]};
            float2 v1 = {acc[mi][ni][2], acc[mi][ni][3]};
            if (EPI == 0) {
                v0.x *= alpha; v0.y *= alpha; v1.x *= alpha; v1.y *= alpha;
                *(float2*)(Cf + (long long)r * ldc + c) = v0;
                *(float2*)(Cf + (long long)(r + 8) * ldc + c) = v1;
            } else if (EPI == 3) {
                *(__half2*)(Ch + (long long)r * ldc + c) = __floats2half2_rn(v0.x, v0.y);
                *(__half2*)(Ch + (long long)(r + 8) * ldc + c) = __floats2half2_rn(v1.x, v1.y);
            } else if (EPI == 2) {
                float bx = bias[c], by = bias[c + 1];
                v0.x += bx; v0.y += by; v1.x += bx; v1.y += by;
                *(float2*)(Cf + (long long)r * ldc + c) = v0;
                *(float2*)(Cf + (long long)(r + 8) * ldc + c) = v1;
                *(__half2*)(Ch + (long long)r * ldc + c) = __floats2half2_rn(v0.x, v0.y);
                *(__half2*)(Ch + (long long)(r + 8) * ldc + c) = __floats2half2_rn(v1.x, v1.y);
            } else {   // EPI == 1
                float2 a0 = *(const float2*)(addend + (long long)r * ldc + c);
                float2 a1 = *(const float2*)(addend + (long long)(r + 8) * ldc + c);
                v0.x += a0.x; v0.y += a0.y;
                v1.x += a1.x; v1.y += a1.y;
                *(float2*)(Cf  + (long long)r * ldc + c) = v0;
                *(float2*)(Cf  + (long long)(r + 8) * ldc + c) = v1;
                *(float2*)(Cf2 + (long long)r * ldc + c) = v0;
                *(float2*)(Cf2 + (long long)(r + 8) * ldc + c) = v1;
            }
        }
    }
}

// ---------------- prep kernels ----------------
__global__ void k_prep_w(const float* __restrict__ w, __half* __restrict__ wc) {
    int i = blockIdx.x * 256 + threadIdx.x;
    if (i < DIM * KIN) {
        int e = i / KIN;
        int r = i - e * KIN;
        int t = r / TOKD;
        int c = r - t * TOKD;
        wc[i] = __float2half_rn(w[e * KIN + c * 5 + t]);
    }
}
__global__ void k_prep_wr(const float* __restrict__ w0, const float* __restrict__ w1,
                          const float* __restrict__ w2, const float* __restrict__ w3,
                          __half* __restrict__ out) {
    int i = blockIdx.x * 256 + threadIdx.x;
    if (i < DIM * DIM) {
        out[i]                 = __float2half_rn(w0[i]);
        out[i + DIM * DIM]     = __float2half_rn(w1[i]);
        out[i + 2 * DIM * DIM] = __float2half_rn(w2[i]);
        out[i + 3 * DIM * DIM] = __float2half_rn(w3[i]);
    }
}
__global__ void k_tohalf(const float* __restrict__ s, __half* __restrict__ d, long long n) {
    long long i = ((long long)blockIdx.x * 256 + threadIdx.x) * 4;
    if (i < n) {
        float4 v = *(const float4*)(s + i);
        *(__half2*)(d + i)     = __floats2half2_rn(v.x, v.y);
        *(__half2*)(d + i + 2) = __floats2half2_rn(v.z, v.w);
    }
}

// transpose per batch (half)
__global__ __launch_bounds__(256) void k_transpose_h(const __half* __restrict__ src,
                                                     __half* __restrict__ dst, int R, int C) {
    __shared__ __half tile[32][34];
    const int b = blockIdx.z;
    src += (long long)b * R * C;
    dst += (long long)b * R * C;
    const int c0 = blockIdx.x * 32, r0 = blockIdx.y * 32;
    const int tx = threadIdx.x & 31, ty = threadIdx.x >> 5;
#pragma unroll
    for (int i = 0; i < 4; i++)
        tile[ty + i * 8][tx] = src[(long long)(r0 + ty + i * 8) * C + c0 + tx];
    __syncthreads();
#pragma unroll
    for (int i = 0; i < 4; i++)
        dst[(long long)(c0 + ty + i * 8) * R + r0 + tx] = tile[tx][ty + i * 8];
}

// ---------------- stat combines ----------------
__global__ void k_row_comb(const float* __restrict__ prm, const float* __restrict__ prs,
                           float* __restrict__ rmax, float* __restrict__ rinv) {
    const int idx = blockIdx.x * 256 + threadIdx.x;      // b*LSEQ + l
    const int b = idx >> 10, l = idx & 1023;
    float m = -1e30f;
#pragma unroll
    for (int t = 0; t < 16; t++) m = fmaxf(m, prm[(b * 16 + t) * LSEQ + l]);
    float s = 0.f;
#pragma unroll
    for (int t = 0; t < 16; t++)
        s += prs[(b * 16 + t) * LSEQ + l] * __expf(prm[(b * 16 + t) * LSEQ + l] - m);
    rmax[idx] = m;
    rinv[idx] = 1.f / s;
}
__global__ void k_col_comb(const float* __restrict__ pcm, const float* __restrict__ pcs,
                           float* __restrict__ cmax, float* __restrict__ cinv) {
    const int idx = blockIdx.x * 256 + threadIdx.x;      // b*SSEQ + s
    const int b = idx >> 11, s0 = idx & 2047;
    float m = -1e30f;
#pragma unroll
    for (int t = 0; t < 8; t++) m = fmaxf(m, pcm[(b * 8 + t) * SSEQ + s0]);
    float s = 0.f;
#pragma unroll
    for (int t = 0; t < 8; t++)
        s += pcs[(b * 8 + t) * SSEQ + s0] * __expf(pcm[(b * 8 + t) * SSEQ + s0] - m);
    cmax[idx] = m;
    cinv[idx] = 1.f / s;
}

// ---------------- apply both softmaxes -> half ----------------
__global__ __launch_bounds__(256) void k_softmax_apply(
    const float* __restrict__ A, __half* __restrict__ Pr, __half* __restrict__ PcT,
    const float* __restrict__ rmax, const float* __restrict__ rinv,
    const float* __restrict__ cmax, const float* __restrict__ cinv)
{
    __shared__ float tile[32][33];
    const int b = blockIdx.z;
    const int s0 = blockIdx.x * 32, l0 = blockIdx.y * 32;
    const float* Ab = A + (long long)b * LSEQ * SSEQ;
    __half* Prb = Pr + (long long)b * LSEQ * SSEQ;
    __half* Pcb = PcT + (long long)b * SSEQ * LSEQ;
    const int tx = threadIdx.x & 31, ty = threadIdx.x >> 5;

    const float cm = cmax[b * SSEQ + s0 + tx];
    const float ci = cinv[b * SSEQ + s0 + tx];
#pragma unroll
    for (int i = 0; i < 4; i++) {
        const int l = l0 + ty + i * 8;
        float v = Ab[(long long)l * SSEQ + s0 + tx];
        Prb[(long long)l * SSEQ + s0 + tx] =
            __float2half_rn(__expf(v - rmax[b * LSEQ + l]) * rinv[b * LSEQ + l]);
        tile[ty + i * 8][tx] = __expf(v - cm) * ci;
    }
    __syncthreads();
#pragma unroll
    for (int i = 0; i < 4; i++) {
        const int s = s0 + ty + i * 8;
        Pcb[(long long)s * LSEQ + l0 + tx] = __float2half_rn(tile[tx][ty + i * 8]);
    }
}

// ---------------- launch ----------------
extern "C" void kernel_launch(void* const* d_in, const int* in_sizes, int n_in,
                              void* d_out, int out_size) {
    const float* latents = (const float*)d_in[0];
    const float* tokens  = (const float*)d_in[1];
    const float* W_lat   = (const float*)d_in[2];
    const float* W_tok   = (const float*)d_in[3];
    const float* W_vlat  = (const float*)d_in[4];
    const float* W_vtok  = (const float*)d_in[5];
    const float* conv_w  = (const float*)d_in[6];
    const float* conv_b  = (const float*)d_in[7];
    float* out = (float*)d_out;

    __half *wcH, *wrH, *toksH, *latH, *tokH, *rlatH, *rtokH, *vlatH, *vtokH, *vlatT, *vtokT, *prH, *pcTH;
    float *tok, *smat, *rmax, *rinv, *cmax, *cinv, *prm, *prs, *pcm, *pcs;
    cudaGetSymbolAddress((void**)&wcH,   g_WcH);
    cudaGetSymbolAddress((void**)&wrH,   g_WrH);
    cudaGetSymbolAddress((void**)&toksH, g_toksH);
    cudaGetSymbolAddress((void**)&latH,  g_latH);
    cudaGetSymbolAddress((void**)&tok,   g_tok);
    cudaGetSymbolAddress((void**)&tokH,  g_tokH);
    cudaGetSymbolAddress((void**)&rlatH, g_RlatH);
    cudaGetSymbolAddress((void**)&rtokH, g_RtokH);
    cudaGetSymbolAddress((void**)&vlatH, g_VlatH);
    cudaGetSymbolAddress((void**)&vtokH, g_VtokH);
    cudaGetSymbolAddress((void**)&vlatT, g_VlatT);
    cudaGetSymbolAddress((void**)&vtokT, g_VtokT);
    cudaGetSymbolAddress((void**)&prH,   g_PrH);
    cudaGetSymbolAddress((void**)&pcTH,  g_PcTH);
    cudaGetSymbolAddress((void**)&smat,  g_S);
    cudaGetSymbolAddress((void**)&rmax,  g_rmax);
    cudaGetSymbolAddress((void**)&rinv,  g_rinv);
    cudaGetSymbolAddress((void**)&cmax,  g_cmax);
    cudaGetSymbolAddress((void**)&cinv,  g_cinv);
    cudaGetSymbolAddress((void**)&prm,   g_prm);
    cudaGetSymbolAddress((void**)&prs,   g_prs);
    cudaGetSymbolAddress((void**)&pcm,   g_pcm);
    cudaGetSymbolAddress((void**)&pcs,   g_pcs);

    cudaFuncSetAttribute(k_gemm_h<0>, cudaFuncAttributeMaxDynamicSharedMemorySize, SM_BYTES);
    cudaFuncSetAttribute(k_gemm_h<1>, cudaFuncAttributeMaxDynamicSharedMemorySize, SM_BYTES);
    cudaFuncSetAttribute(k_gemm_h<2>, cudaFuncAttributeMaxDynamicSharedMemorySize, SM_BYTES);
    cudaFuncSetAttribute(k_gemm_h<3>, cudaFuncAttributeMaxDynamicSharedMemorySize, SM_BYTES);
    cudaFuncSetAttribute(k_gemm_h<4>, cudaFuncAttributeMaxDynamicSharedMemorySize, SM_BYTES);

    const long long UL = (long long)NB * LSEQ * DIM;
    const long long UT = (long long)NB * SSEQ * DIM;
    const long long CONCAT = UL + UT;

    const long long NTOK = (long long)NB * TOKS * TOKD;
    const long long NLAT = (long long)NB * LSEQ * DIM;
    k_tohalf<<<(int)(NTOK / 4 / 256), 256>>>(tokens, toksH, NTOK);
    k_tohalf<<<(int)(NLAT / 4 / 256), 256>>>(latents, latH, NLAT);
    k_prep_w<<<(DIM * KIN + 255) / 256, 256>>>(conv_w, wcH);
    k_prep_wr<<<(DIM * DIM + 255) / 256, 256>>>(W_lat, W_tok, W_vlat, W_vtok, wrH);

    // conv as GEMM
    k_gemm_h<2><<<dim3(DIM / BN, (NB * SSEQ) / BM, 1), 128, SM_BYTES>>>(
        toksH, wcH, tok, nullptr, tokH, KIN, KIN, KIN, DIM, 0, 0, 0, 0,
        1.f, conv_b, nullptr, 0, nullptr, nullptr, nullptr, nullptr);

    // projections
    k_gemm_h<3><<<dim3(DIM / BN, (NB * LSEQ) / BM, 1), 128, SM_BYTES>>>(
        latH, wrH + 0 * DIM * DIM, nullptr, nullptr, rlatH, DIM, DIM, DIM, DIM, 0, 0, 0, 0,
        1.f, nullptr, nullptr, 0, nullptr, nullptr, nullptr, nullptr);
    k_gemm_h<3><<<dim3(DIM / BN, (NB * LSEQ) / BM, 1), 128, SM_BYTES>>>(
        latH, wrH + 2 * DIM * DIM, nullptr, nullptr, vlatH, DIM, DIM, DIM, DIM, 0, 0, 0, 0,
        1.f, nullptr, nullptr, 0, nullptr, nullptr, nullptr, nullptr);
    k_gemm_h<3><<<dim3(DIM / BN, (NB * SSEQ) / BM, 1), 128, SM_BYTES>>>(
        tokH, wrH + 1 * DIM * DIM, nullptr, nullptr, rtokH, DIM, DIM, DIM, DIM, 0, 0, 0, 0,
        1.f, nullptr, nullptr, 0, nullptr, nullptr, nullptr, nullptr);
    k_gemm_h<3><<<dim3(DIM / BN, (NB * SSEQ) / BM, 1), 128, SM_BYTES>>>(
        tokH, wrH + 3 * DIM * DIM, nullptr, nullptr, vtokH, DIM, DIM, DIM, DIM, 0, 0, 0, 0,
        1.f, nullptr, nullptr, 0, nullptr, nullptr, nullptr, nullptr);

    // V transposes
    k_transpose_h<<<dim3(DIM / 32, LSEQ / 32, NB), 256>>>(vlatH, vlatT, LSEQ, DIM);
    k_transpose_h<<<dim3(DIM / 32, SSEQ / 32, NB), 256>>>(vtokH, vtokT, SSEQ, DIM);

    // scores + fused tile-partial softmax stats
    const float scale = 0.044194173824159216f;
    k_gemm_h<4><<<dim3(SSEQ / BN, LSEQ / BM, NB), 128, SM_BYTES>>>(
        rlatH, rtokH, smat, nullptr, nullptr, DIM, DIM, DIM, SSEQ,
        (long long)LSEQ * DIM, (long long)SSEQ * DIM, (long long)LSEQ * SSEQ, 0,
        scale, nullptr, nullptr, 0, prm, prs, pcm, pcs);

    // combine stats + apply
    k_row_comb<<<NB * LSEQ / 256, 256>>>(prm, prs, rmax, rinv);
    k_col_comb<<<NB * SSEQ / 256, 256>>>(pcm, pcs, cmax, cinv);
    k_softmax_apply<<<dim3(SSEQ / 32, LSEQ / 32, NB), 256>>>(
        smat, prH, pcTH, rmax, rinv, cmax, cinv);

    // delta_lat = Prow @ VtokT^T + latents
    k_gemm_h<1><<<dim3(DIM / BN, LSEQ / BM, NB), 128, SM_BYTES>>>(
        prH, vtokT, out, out + CONCAT, nullptr, SSEQ, SSEQ, SSEQ, DIM,
        (long long)LSEQ * SSEQ, (long long)DIM * SSEQ,
        (long long)LSEQ * DIM, (long long)(LSEQ + SSEQ) * DIM,
        1.f, nullptr, latents, (long long)LSEQ * DIM, nullptr, nullptr, nullptr, nullptr);

    // delta_tok = PcT @ VlatT^T + tok
    k_gemm_h<1><<<dim3(DIM / BN, SSEQ / BM, NB), 128, SM_BYTES>>>(
        pcTH, vlatT, out + UL, out + CONCAT + (long long)LSEQ * DIM, nullptr, LSEQ, LSEQ, LSEQ, DIM,
        (long long)SSEQ * LSEQ, (long long)DIM * LSEQ,
        (long long)SSEQ * DIM, (long long)(LSEQ + SSEQ) * DIM,
        1.f, nullptr, tok, (long long)SSEQ * DIM, nullptr, nullptr, nullptr, nullptr);
}

// round 10
// speedup vs baseline: 2.2076x; 1.0952x over previous
#include <cuda_runtime.h>
#include <cuda_fp16.h>
#include <math.h>
#include <stdint.h>

// ---------------- problem constants ----------------
#define NB   8
#define LSEQ 1024
#define SSEQ 2048
#define DIM  512
#define TOKD 256
#define KIN  1280
#define TOKS 10240

// ---------------- scratch ----------------
__device__ __align__(256) __half g_WcH  [DIM * KIN];
__device__ __align__(256) __half g_WrH  [4 * DIM * DIM];   // [Wlat, Wvlat, Wtok, Wvtok]
__device__ __align__(256) __half g_toksH[NB * TOKS * TOKD];
__device__ __align__(256) __half g_latH [NB * LSEQ * DIM];
__device__ __align__(256) float  g_tok  [NB * SSEQ * DIM];
__device__ __align__(256) __half g_tokH [NB * SSEQ * DIM];
__device__ __align__(256) __half g_RlatH[NB * LSEQ * DIM];
__device__ __align__(256) __half g_RtokH[NB * SSEQ * DIM];
__device__ __align__(256) __half g_VlatH[NB * LSEQ * DIM];
__device__ __align__(256) __half g_VtokH[NB * SSEQ * DIM];
__device__ __align__(256) __half g_VlatT[NB * DIM * LSEQ];
__device__ __align__(256) __half g_VtokT[NB * DIM * SSEQ];
__device__ __align__(256) float  g_S    [NB * LSEQ * SSEQ];
__device__ __align__(256) __half g_PrH  [NB * LSEQ * SSEQ];
__device__ __align__(256) __half g_PcTH [NB * SSEQ * LSEQ];
__device__ __align__(256) float  g_rmax [NB * LSEQ];
__device__ __align__(256) float  g_rinv [NB * LSEQ];
__device__ __align__(256) float  g_cmax [NB * SSEQ];
__device__ __align__(256) float  g_cinv [NB * SSEQ];
__device__ __align__(256) float  g_prm  [NB * 16 * LSEQ];
__device__ __align__(256) float  g_prs  [NB * 16 * LSEQ];
__device__ __align__(256) float  g_pcm  [NB * 8 * SSEQ];
__device__ __align__(256) float  g_pcs  [NB * 8 * SSEQ];

// ---------------- GEMM config ----------------
#define BM 128
#define BN 128
#define BK 32
#define PH 40
#define STAGES 4
#define ASZH (BM * PH)
#define BSZH (BN * PH)
#define SM_BYTES (STAGES * (ASZH + BSZH) * 2)   // 81920

__device__ __forceinline__ void mma_f16(float c[4], const uint32_t a[4], const uint32_t b[2]) {
    asm volatile(
        "mma.sync.aligned.m16n8k16.row.col.f32.f16.f16.f32 "
        "{%0,%1,%2,%3}, {%4,%5,%6,%7}, {%8,%9}, {%0,%1,%2,%3};"
        : "+f"(c[0]), "+f"(c[1]), "+f"(c[2]), "+f"(c[3])
        : "r"(a[0]), "r"(a[1]), "r"(a[2]), "r"(a[3]), "r"(b[0]), "r"(b[1]));
}

__device__ __forceinline__ void ldsm_x4(uint32_t r[4], uint32_t addr) {
    asm volatile("ldmatrix.sync.aligned.m8n8.x4.shared.b16 {%0,%1,%2,%3}, [%4];"
                 : "=r"(r[0]), "=r"(r[1]), "=r"(r[2]), "=r"(r[3]) : "r"(addr));
}

__device__ __forceinline__ void cpasync16(uint32_t dst, const void* src) {
    asm volatile("cp.async.cg.shared.global [%0], [%1], 16;" :: "r"(dst), "l"(src));
}

__device__ __forceinline__ void msmerge(float& m, float& s, float om, float os) {
    float M = fmaxf(m, om);
    s = s * __expf(m - M) + os * __expf(om - M);
    m = M;
}

// ---------------- shared GEMM mainloop: acc += A(M,K) @ B(N,K)^T tile ----------------
__device__ __forceinline__ void gemm_core(
    const __half* __restrict__ A, const __half* __restrict__ B,
    int lda, int ldb, int tiles, int m0, int n0, float (&acc)[4][8][4])
{
    extern __shared__ __half smh[];
    const uint32_t sbase = (uint32_t)__cvta_generic_to_shared(smh);
    const uint32_t aReg = sbase;
    const uint32_t bReg = sbase + STAGES * ASZH * 2;
    const int tid = threadIdx.x;
    const int wid = tid >> 5, lane = tid & 31;
    const int wm = (wid >> 1) * 64, wn = (wid & 1) * 64;

    uint32_t aAddr[4], bAddr[4];
    {
        const int r = lane & 7;
        const int aRowOff = ((lane >> 3) & 1) * 8 + r;
        const int aChunk = lane >> 4;
#pragma unroll
        for (int mi = 0; mi < 4; mi++)
            aAddr[mi] = aReg + (uint32_t)((wm + mi * 16 + aRowOff) * PH + aChunk * 8) * 2;
        const int bRow = (lane >> 4);
        const int bChunk = (lane >> 3) & 1;
#pragma unroll
        for (int p = 0; p < 4; p++)
            bAddr[p] = bReg + (uint32_t)((wn + (2 * p + bRow) * 8 + r) * PH + bChunk * 8) * 2;
    }

#pragma unroll
    for (int i = 0; i < 4; i++)
#pragma unroll
        for (int j = 0; j < 8; j++)
#pragma unroll
            for (int r = 0; r < 4; r++) acc[i][j][r] = 0.f;

    auto loadTile = [&](int t, int buf) {
        const int k0 = t * BK;
        const uint32_t Ab = aReg + buf * ASZH * 2;
        const uint32_t Bb = bReg + buf * BSZH * 2;
#pragma unroll
        for (int i = 0; i < 4; i++) {
            int idx = i * 128 + tid;
            int row = idx >> 2, seg = idx & 3;
            cpasync16(Ab + (uint32_t)(row * PH + seg * 8) * 2,
                      A + (long long)(m0 + row) * lda + k0 + seg * 8);
        }
#pragma unroll
        for (int i = 0; i < 4; i++) {
            int idx = i * 128 + tid;
            int row = idx >> 2, seg = idx & 3;
            cpasync16(Bb + (uint32_t)(row * PH + seg * 8) * 2,
                      B + (long long)(n0 + row) * ldb + k0 + seg * 8);
        }
        asm volatile("cp.async.commit_group;");
    };

    auto compute = [&](int buf) {
        const uint32_t aOff = buf * ASZH * 2;
        const uint32_t bOff = buf * BSZH * 2;
#pragma unroll
        for (int ks = 0; ks < 2; ks++) {
            uint32_t af[4][4], bf[8][2];
#pragma unroll
            for (int mi = 0; mi < 4; mi++)
                ldsm_x4(af[mi], aAddr[mi] + aOff + ks * 32);
#pragma unroll
            for (int p = 0; p < 4; p++) {
                uint32_t t4[4];
                ldsm_x4(t4, bAddr[p] + bOff + ks * 32);
                bf[2 * p][0] = t4[0]; bf[2 * p][1] = t4[1];
                bf[2 * p + 1][0] = t4[2]; bf[2 * p + 1][1] = t4[3];
            }
#pragma unroll
            for (int mi = 0; mi < 4; mi++)
#pragma unroll
                for (int ni = 0; ni < 8; ni++)
                    mma_f16(acc[mi][ni], af[mi], bf[ni]);
        }
    };

    loadTile(0, 0);
    loadTile(1, 1);
    loadTile(2, 2);
    for (int t = 0; t < tiles; t++) {
        // correct tail semantics: once no group beyond t+2 exists, drain fully
        if (t + 2 < tiles) asm volatile("cp.async.wait_group 2;");
        else               asm volatile("cp.async.wait_group 0;");
        __syncthreads();                         // all warps done with buf (t-1)%4 & stage t visible
        if (t + 3 < tiles) loadTile(t + 3, (t + 3) & 3);   // writes buf (t-1)%4
        compute(t & 3);
    }
}

// ---------------- conv GEMM: Cf = acc + bias (f32), Ch = half ----------------
__global__ __launch_bounds__(128, 2) void k_conv(
    const __half* __restrict__ A, const __half* __restrict__ B,
    float* __restrict__ Cf, __half* __restrict__ Ch, const float* __restrict__ bias)
{
    const int m0 = blockIdx.y * BM, n0 = blockIdx.x * BN;
    float acc[4][8][4];
    gemm_core(A, B, KIN, KIN, KIN / BK, m0, n0, acc);
    const int tid = threadIdx.x, wid = tid >> 5, lane = tid & 31;
    const int grp = lane >> 2, tig = lane & 3;
    const int wm = (wid >> 1) * 64, wn = (wid & 1) * 64;
#pragma unroll
    for (int mi = 0; mi < 4; mi++) {
        const int r = m0 + wm + mi * 16 + grp;
#pragma unroll
        for (int ni = 0; ni < 8; ni++) {
            const int c = n0 + wn + ni * 8 + tig * 2;
            float bx = bias[c], by = bias[c + 1];
            float2 v0 = {acc[mi][ni][0] + bx, acc[mi][ni][1] + by};
            float2 v1 = {acc[mi][ni][2] + bx, acc[mi][ni][3] + by};
            *(float2*)(Cf + (long long)r * DIM + c) = v0;
            *(float2*)(Cf + (long long)(r + 8) * DIM + c) = v1;
            *(__half2*)(Ch + (long long)r * DIM + c) = __floats2half2_rn(v0.x, v0.y);
            *(__half2*)(Ch + (long long)(r + 8) * DIM + c) = __floats2half2_rn(v1.x, v1.y);
        }
    }
}

// ---------------- merged R/V projection: N=1024 stacked weights ----------------
__global__ __launch_bounds__(128, 2) void k_proj(
    const __half* __restrict__ A, const __half* __restrict__ W,
    __half* __restrict__ Rdst, __half* __restrict__ Vdst)
{
    const int m0 = blockIdx.y * BM, n0 = blockIdx.x * BN;
    float acc[4][8][4];
    gemm_core(A, W, DIM, DIM, DIM / BK, m0, n0, acc);
    const int tid = threadIdx.x, wid = tid >> 5, lane = tid & 31;
    const int grp = lane >> 2, tig = lane & 3;
    const int wm = (wid >> 1) * 64, wn = (wid & 1) * 64;
    __half* dst = (n0 < DIM) ? Rdst : Vdst;
    const int cb = (n0 < DIM) ? 0 : DIM;
#pragma unroll
    for (int mi = 0; mi < 4; mi++) {
        const int r = m0 + wm + mi * 16 + grp;
#pragma unroll
        for (int ni = 0; ni < 8; ni++) {
            const int c = n0 + wn + ni * 8 + tig * 2 - cb;
            *(__half2*)(dst + (long long)r * DIM + c) =
                __floats2half2_rn(acc[mi][ni][0], acc[mi][ni][1]);
            *(__half2*)(dst + (long long)(r + 8) * DIM + c) =
                __floats2half2_rn(acc[mi][ni][2], acc[mi][ni][3]);
        }
    }
}

// ---------------- scores GEMM + fused tile-partial stats ----------------
__global__ __launch_bounds__(128, 2) void k_scores(
    const __half* __restrict__ Aall, const __half* __restrict__ Ball, float alpha)
{
    const long long z = blockIdx.z;
    const __half* A = Aall + z * (long long)LSEQ * DIM;
    const __half* B = Ball + z * (long long)SSEQ * DIM;
    float* Cf = g_S + z * (long long)LSEQ * SSEQ;
    const int m0 = blockIdx.y * BM, n0 = blockIdx.x * BN;

    float acc[4][8][4];
    gemm_core(A, B, DIM, DIM, DIM / BK, m0, n0, acc);

    const int tid = threadIdx.x, wid = tid >> 5, lane = tid & 31;
    const int grp = lane >> 2, tig = lane & 3;
    const int wm = (wid >> 1) * 64, wn = (wid & 1) * 64;

#pragma unroll
    for (int mi = 0; mi < 4; mi++)
#pragma unroll
        for (int ni = 0; ni < 8; ni++)
#pragma unroll
            for (int r = 0; r < 4; r++) acc[mi][ni][r] *= alpha;
#pragma unroll
    for (int mi = 0; mi < 4; mi++) {
        const int r = m0 + wm + mi * 16 + grp;
#pragma unroll
        for (int ni = 0; ni < 8; ni++) {
            const int c = n0 + wn + ni * 8 + tig * 2;
            *(float2*)(Cf + (long long)r * SSEQ + c) = make_float2(acc[mi][ni][0], acc[mi][ni][1]);
            *(float2*)(Cf + (long long)(r + 8) * SSEQ + c) = make_float2(acc[mi][ni][2], acc[mi][ni][3]);
        }
    }
    extern __shared__ __half smh[];
    float* smf = (float*)smh;
    __syncthreads();
    // row partials
#pragma unroll
    for (int mi = 0; mi < 4; mi++) {
#pragma unroll
        for (int h = 0; h < 2; h++) {
            float m = -1e30f;
#pragma unroll
            for (int ni = 0; ni < 8; ni++) {
                m = fmaxf(m, acc[mi][ni][2 * h]);
                m = fmaxf(m, acc[mi][ni][2 * h + 1]);
            }
            float s = 0.f;
#pragma unroll
            for (int ni = 0; ni < 8; ni++) {
                s += __expf(acc[mi][ni][2 * h] - m);
                s += __expf(acc[mi][ni][2 * h + 1] - m);
            }
#pragma unroll
            for (int off = 1; off <= 2; off <<= 1) {
                float om = __shfl_xor_sync(0xffffffffu, m, off);
                float os = __shfl_xor_sync(0xffffffffu, s, off);
                msmerge(m, s, om, os);
            }
            if (tig == 0) {
                int lr = mi * 16 + grp + 8 * h;
                smf[(wid * 64 + lr) * 2 + 0] = m;
                smf[(wid * 64 + lr) * 2 + 1] = s;
            }
        }
    }
    __syncthreads();
    if (tid < 128) {
        const int r = tid;
        const int w0 = (r >> 6) * 2, lr = r & 63;
        float m = smf[(w0 * 64 + lr) * 2 + 0];
        float s = smf[(w0 * 64 + lr) * 2 + 1];
        msmerge(m, s, smf[((w0 + 1) * 64 + lr) * 2 + 0], smf[((w0 + 1) * 64 + lr) * 2 + 1]);
        const long long idx = (z * 16 + blockIdx.x) * LSEQ + m0 + r;
        g_prm[idx] = m;
        g_prs[idx] = s;
    }
    __syncthreads();
    // col partials
#pragma unroll
    for (int ni = 0; ni < 8; ni++) {
#pragma unroll
        for (int j = 0; j < 2; j++) {
            float m = -1e30f;
#pragma unroll
            for (int mi = 0; mi < 4; mi++) {
                m = fmaxf(m, acc[mi][ni][j]);
                m = fmaxf(m, acc[mi][ni][2 + j]);
            }
            float s = 0.f;
#pragma unroll
            for (int mi = 0; mi < 4; mi++) {
                s += __expf(acc[mi][ni][j] - m);
                s += __expf(acc[mi][ni][2 + j] - m);
            }
#pragma unroll
            for (int off = 4; off <= 16; off <<= 1) {
                float om = __shfl_xor_sync(0xffffffffu, m, off);
                float os = __shfl_xor_sync(0xffffffffu, s, off);
                msmerge(m, s, om, os);
            }
            if (grp == 0) {
                int lc = ni * 8 + tig * 2 + j;
                smf[(wid * 64 + lc) * 2 + 0] = m;
                smf[(wid * 64 + lc) * 2 + 1] = s;
            }
        }
    }
    __syncthreads();
    if (tid < 128) {
        const int c = tid;
        const int w0 = (c >> 6), lc = c & 63;
        float m = smf[(w0 * 64 + lc) * 2 + 0];
        float s = smf[(w0 * 64 + lc) * 2 + 1];
        msmerge(m, s, smf[((w0 + 2) * 64 + lc) * 2 + 0], smf[((w0 + 2) * 64 + lc) * 2 + 1]);
        const long long idx = (z * 8 + blockIdx.y) * SSEQ + n0 + c;
        g_pcm[idx] = m;
        g_pcs[idx] = s;
    }
}

// ---------------- merged delta GEMM (both attention outputs, one launch) ----------------
__global__ __launch_bounds__(128, 2) void k_delta(
    const float* __restrict__ latents, float* __restrict__ out)
{
    constexpr long long UL = (long long)NB * LSEQ * DIM;
    constexpr long long UT = (long long)NB * SSEQ * DIM;
    constexpr long long CONCAT = UL + UT;

    const long long z = blockIdx.z;
    const __half *A, *Bm;
    const float* addend;
    float *Cf, *Cf2;
    int lda, K, m0;
    if (blockIdx.y < 8) {
        A = g_PrH + z * (long long)LSEQ * SSEQ;  lda = SSEQ; K = SSEQ;
        Bm = g_VtokT + z * (long long)DIM * SSEQ;
        addend = latents + z * (long long)LSEQ * DIM;
        Cf = out + z * (long long)LSEQ * DIM;
        Cf2 = out + CONCAT + z * (long long)(LSEQ + SSEQ) * DIM;
        m0 = blockIdx.y * BM;
    } else {
        A = g_PcTH + z * (long long)SSEQ * LSEQ; lda = LSEQ; K = LSEQ;
        Bm = g_VlatT + z * (long long)DIM * LSEQ;
        addend = g_tok + z * (long long)SSEQ * DIM;
        Cf = out + UL + z * (long long)SSEQ * DIM;
        Cf2 = out + CONCAT + (long long)LSEQ * DIM + z * (long long)(LSEQ + SSEQ) * DIM;
        m0 = (blockIdx.y - 8) * BM;
    }
    const int n0 = blockIdx.x * BN;

    float acc[4][8][4];
    gemm_core(A, Bm, lda, lda, K / BK, m0, n0, acc);

    const int tid = threadIdx.x, wid = tid >> 5, lane = tid & 31;
    const int grp = lane >> 2, tig = lane & 3;
    const int wm = (wid >> 1) * 64, wn = (wid & 1) * 64;
#pragma unroll
    for (int mi = 0; mi < 4; mi++) {
        const int r = m0 + wm + mi * 16 + grp;
#pragma unroll
        for (int ni = 0; ni < 8; ni++) {
            const int c = n0 + wn + ni * 8 + tig * 2;
            float2 a0 = *(const float2*)(addend + (long long)r * DIM + c);
            float2 a1 = *(const float2*)(addend + (long long)(r + 8) * DIM + c);
            float2 v0 = {acc[mi][ni][0] + a0.x, acc[mi][ni][1] + a0.y};
            float2 v1 = {acc[mi][ni][2] + a1.x, acc[mi][ni][3] + a1.y};
            *(float2*)(Cf  + (long long)r * DIM + c) = v0;
            *(float2*)(Cf  + (long long)(r + 8) * DIM + c) = v1;
            *(float2*)(Cf2 + (long long)r * DIM + c) = v0;
            *(float2*)(Cf2 + (long long)(r + 8) * DIM + c) = v1;
        }
    }
}

// ---------------- prep kernels ----------------
__global__ void k_prep_w(const float* __restrict__ w, __half* __restrict__ wc) {
    int i = blockIdx.x * 256 + threadIdx.x;
    if (i < DIM * KIN) {
        int e = i / KIN;
        int r = i - e * KIN;
        int t = r / TOKD;
        int c = r - t * TOKD;
        wc[i] = __float2half_rn(w[e * KIN + c * 5 + t]);
    }
}
__global__ void k_prep_wr(const float* __restrict__ w0, const float* __restrict__ w1,
                          const float* __restrict__ w2, const float* __restrict__ w3,
                          __half* __restrict__ out) {
    int i = blockIdx.x * 256 + threadIdx.x;
    if (i < DIM * DIM) {
        out[i]                 = __float2half_rn(w0[i]);   // Wlat
        out[i + DIM * DIM]     = __float2half_rn(w1[i]);   // Wvlat
        out[i + 2 * DIM * DIM] = __float2half_rn(w2[i]);   // Wtok
        out[i + 3 * DIM * DIM] = __float2half_rn(w3[i]);   // Wvtok
    }
}
__global__ void k_tohalf(const float* __restrict__ s, __half* __restrict__ d, long long n) {
    long long i = ((long long)blockIdx.x * 256 + threadIdx.x) * 4;
    if (i < n) {
        float4 v = *(const float4*)(s + i);
        *(__half2*)(d + i)     = __floats2half2_rn(v.x, v.y);
        *(__half2*)(d + i + 2) = __floats2half2_rn(v.z, v.w);
    }
}

__global__ __launch_bounds__(256) void k_transpose_h(const __half* __restrict__ src,
                                                     __half* __restrict__ dst, int R, int C) {
    __shared__ __half tile[32][34];
    const int b = blockIdx.z;
    src += (long long)b * R * C;
    dst += (long long)b * R * C;
    const int c0 = blockIdx.x * 32, r0 = blockIdx.y * 32;
    const int tx = threadIdx.x & 31, ty = threadIdx.x >> 5;
#pragma unroll
    for (int i = 0; i < 4; i++)
        tile[ty + i * 8][tx] = src[(long long)(r0 + ty + i * 8) * C + c0 + tx];
    __syncthreads();
#pragma unroll
    for (int i = 0; i < 4; i++)
        dst[(long long)(c0 + ty + i * 8) * R + r0 + tx] = tile[tx][ty + i * 8];
}

// ---------------- stat combines ----------------
__global__ void k_row_comb(float* __restrict__ rmax, float* __restrict__ rinv) {
    const int idx = blockIdx.x * 256 + threadIdx.x;
    const int b = idx >> 10, l = idx & 1023;
    float m = -1e30f;
#pragma unroll
    for (int t = 0; t < 16; t++) m = fmaxf(m, g_prm[(b * 16 + t) * LSEQ + l]);
    float s = 0.f;
#pragma unroll
    for (int t = 0; t < 16; t++)
        s += g_prs[(b * 16 + t) * LSEQ + l] * __expf(g_prm[(b * 16 + t) * LSEQ + l] - m);
    rmax[idx] = m;
    rinv[idx] = 1.f / s;
}
__global__ void k_col_comb(float* __restrict__ cmax, float* __restrict__ cinv) {
    const int idx = blockIdx.x * 256 + threadIdx.x;
    const int b = idx >> 11, s0 = idx & 2047;
    float m = -1e30f;
#pragma unroll
    for (int t = 0; t < 8; t++) m = fmaxf(m, g_pcm[(b * 8 + t) * SSEQ + s0]);
    float s = 0.f;
#pragma unroll
    for (int t = 0; t < 8; t++)
        s += g_pcs[(b * 8 + t) * SSEQ + s0] * __expf(g_pcm[(b * 8 + t) * SSEQ + s0] - m);
    cmax[idx] = m;
    cinv[idx] = 1.f / s;
}

// ---------------- apply both softmaxes -> half ----------------
__global__ __launch_bounds__(256) void k_softmax_apply(
    const float* __restrict__ A, __half* __restrict__ Pr, __half* __restrict__ PcT,
    const float* __restrict__ rmax, const float* __restrict__ rinv,
    const float* __restrict__ cmax, const float* __restrict__ cinv)
{
    __shared__ float tile[32][33];
    const int b = blockIdx.z;
    const int s0 = blockIdx.x * 32, l0 = blockIdx.y * 32;
    const float* Ab = A + (long long)b * LSEQ * SSEQ;
    __half* Prb = Pr + (long long)b * LSEQ * SSEQ;
    __half* Pcb = PcT + (long long)b * SSEQ * LSEQ;
    const int tx = threadIdx.x & 31, ty = threadIdx.x >> 5;

    const float cm = cmax[b * SSEQ + s0 + tx];
    const float ci = cinv[b * SSEQ + s0 + tx];
#pragma unroll
    for (int i = 0; i < 4; i++) {
        const int l = l0 + ty + i * 8;
        float v = Ab[(long long)l * SSEQ + s0 + tx];
        Prb[(long long)l * SSEQ + s0 + tx] =
            __float2half_rn(__expf(v - rmax[b * LSEQ + l]) * rinv[b * LSEQ + l]);
        tile[ty + i * 8][tx] = __expf(v - cm) * ci;
    }
    __syncthreads();
#pragma unroll
    for (int i = 0; i < 4; i++) {
        const int s = s0 + ty + i * 8;
        Pcb[(long long)s * LSEQ + l0 + tx] = __float2half_rn(tile[tx][ty + i * 8]);
    }
}

// ---------------- launch ----------------
extern "C" void kernel_launch(void* const* d_in, const int* in_sizes, int n_in,
                              void* d_out, int out_size) {
    const float* latents = (const float*)d_in[0];
    const float* tokens  = (const float*)d_in[1];
    const float* W_lat   = (const float*)d_in[2];
    const float* W_tok   = (const float*)d_in[3];
    const float* W_vlat  = (const float*)d_in[4];
    const float* W_vtok  = (const float*)d_in[5];
    const float* conv_w  = (const float*)d_in[6];
    const float* conv_b  = (const float*)d_in[7];
    float* out = (float*)d_out;

    __half *wcH, *wrH, *toksH, *latH, *tokH, *rlatH, *rtokH, *vlatH, *vtokH, *vlatT, *vtokT, *prH, *pcTH;
    float *tok, *smat, *rmax, *rinv, *cmax, *cinv;
    cudaGetSymbolAddress((void**)&wcH,   g_WcH);
    cudaGetSymbolAddress((void**)&wrH,   g_WrH);
    cudaGetSymbolAddress((void**)&toksH, g_toksH);
    cudaGetSymbolAddress((void**)&latH,  g_latH);
    cudaGetSymbolAddress((void**)&tok,   g_tok);
    cudaGetSymbolAddress((void**)&tokH,  g_tokH);
    cudaGetSymbolAddress((void**)&rlatH, g_RlatH);
    cudaGetSymbolAddress((void**)&rtokH, g_RtokH);
    cudaGetSymbolAddress((void**)&vlatH, g_VlatH);
    cudaGetSymbolAddress((void**)&vtokH, g_VtokH);
    cudaGetSymbolAddress((void**)&vlatT, g_VlatT);
    cudaGetSymbolAddress((void**)&vtokT, g_VtokT);
    cudaGetSymbolAddress((void**)&prH,   g_PrH);
    cudaGetSymbolAddress((void**)&pcTH,  g_PcTH);
    cudaGetSymbolAddress((void**)&smat,  g_S);
    cudaGetSymbolAddress((void**)&rmax,  g_rmax);
    cudaGetSymbolAddress((void**)&rinv,  g_rinv);
    cudaGetSymbolAddress((void**)&cmax,  g_cmax);
    cudaGetSymbolAddress((void**)&cinv,  g_cinv);

    cudaFuncSetAttribute(k_conv,   cudaFuncAttributeMaxDynamicSharedMemorySize, SM_BYTES);
    cudaFuncSetAttribute(k_proj,   cudaFuncAttributeMaxDynamicSharedMemorySize, SM_BYTES);
    cudaFuncSetAttribute(k_scores, cudaFuncAttributeMaxDynamicSharedMemorySize, SM_BYTES);
    cudaFuncSetAttribute(k_delta,  cudaFuncAttributeMaxDynamicSharedMemorySize, SM_BYTES);

    const long long NTOK = (long long)NB * TOKS * TOKD;
    const long long NLAT = (long long)NB * LSEQ * DIM;
    k_tohalf<<<(int)(NTOK / 4 / 256), 256>>>(tokens, toksH, NTOK);
    k_tohalf<<<(int)(NLAT / 4 / 256), 256>>>(latents, latH, NLAT);
    k_prep_w<<<(DIM * KIN + 255) / 256, 256>>>(conv_w, wcH);
    k_prep_wr<<<(DIM * DIM + 255) / 256, 256>>>(W_lat, W_vlat, W_tok, W_vtok, wrH);

    // conv as GEMM
    k_conv<<<dim3(DIM / BN, (NB * SSEQ) / BM), 128, SM_BYTES>>>(toksH, wcH, tok, tokH, conv_b);

    // merged projections: lat -> (Rlat, Vlat), tok -> (Rtok, Vtok)
    k_proj<<<dim3(2 * DIM / BN, (NB * LSEQ) / BM), 128, SM_BYTES>>>(
        latH, wrH, rlatH, vlatH);
    k_proj<<<dim3(2 * DIM / BN, (NB * SSEQ) / BM), 128, SM_BYTES>>>(
        tokH, wrH + 2 * DIM * DIM, rtokH, vtokH);

    // V transposes
    k_transpose_h<<<dim3(DIM / 32, LSEQ / 32, NB), 256>>>(vlatH, vlatT, LSEQ, DIM);
    k_transpose_h<<<dim3(DIM / 32, SSEQ / 32, NB), 256>>>(vtokH, vtokT, SSEQ, DIM);

    // scores + fused stats
    const float scale = 0.044194173824159216f;
    k_scores<<<dim3(SSEQ / BN, LSEQ / BM, NB), 128, SM_BYTES>>>(rlatH, rtokH, scale);

    // combine + apply
    k_row_comb<<<NB * LSEQ / 256, 256>>>(rmax, rinv);
    k_col_comb<<<NB * SSEQ / 256, 256>>>(cmax, cinv);
    k_softmax_apply<<<dim3(SSEQ / 32, LSEQ / 32, NB), 256>>>(
        smat, prH, pcTH, rmax, rinv, cmax, cinv);

    // merged delta (both attention GEMMs)
    k_delta<<<dim3(DIM / BN, 24, NB), 128, SM_BYTES>>>(latents, out);
}

// round 11
// speedup vs baseline: 2.2946x; 1.0394x over previous
#include <cuda_runtime.h>
#include <cuda_fp16.h>
#include <math.h>
#include <stdint.h>

// ---------------- problem constants ----------------
#define NB   8
#define LSEQ 1024
#define SSEQ 2048
#define DIM  512
#define TOKD 256
#define KIN  1280
#define TOKS 10240

// ---------------- scratch ----------------
__device__ __align__(256) __half g_WcH  [DIM * KIN];
__device__ __align__(256) __half g_WrH  [4 * DIM * DIM];   // [Wlat, Wvlat, Wtok, Wvtok]
__device__ __align__(256) __half g_toksH[NB * TOKS * TOKD];
__device__ __align__(256) __half g_latH [NB * LSEQ * DIM];
__device__ __align__(256) float  g_tok  [NB * SSEQ * DIM];
__device__ __align__(256) __half g_tokH [NB * SSEQ * DIM];
__device__ __align__(256) __half g_RlatH[NB * LSEQ * DIM];
__device__ __align__(256) __half g_RtokH[NB * SSEQ * DIM];
__device__ __align__(256) __half g_VlatT[NB * DIM * LSEQ];   // (E, L), written directly by proj
__device__ __align__(256) __half g_VtokT[NB * DIM * SSEQ];   // (E, S)
__device__ __align__(256) float  g_S    [NB * LSEQ * SSEQ];
__device__ __align__(256) __half g_PrH  [NB * LSEQ * SSEQ];
__device__ __align__(256) __half g_PcTH [NB * SSEQ * LSEQ];
__device__ __align__(256) float  g_rmax [NB * LSEQ];
__device__ __align__(256) float  g_rinv [NB * LSEQ];
__device__ __align__(256) float  g_cmax [NB * SSEQ];
__device__ __align__(256) float  g_cinv [NB * SSEQ];
__device__ __align__(256) float  g_prm  [NB * 16 * LSEQ];
__device__ __align__(256) float  g_prs  [NB * 16 * LSEQ];
__device__ __align__(256) float  g_pcm  [NB * 8 * SSEQ];
__device__ __align__(256) float  g_pcs  [NB * 8 * SSEQ];

// ---------------- GEMM config ----------------
#define BM 128
#define BN 128
#define BK 32
#define PH 40
#define STAGES 4
#define ASZH (BM * PH)
#define BSZH (BN * PH)
#define SM_BYTES (STAGES * (ASZH + BSZH) * 2)   // 81920
#define TSTR 136                                 // epilogue transpose stage stride (halves)

__device__ __forceinline__ void mma_f16(float c[4], const uint32_t a[4], const uint32_t b[2]) {
    asm volatile(
        "mma.sync.aligned.m16n8k16.row.col.f32.f16.f16.f32 "
        "{%0,%1,%2,%3}, {%4,%5,%6,%7}, {%8,%9}, {%0,%1,%2,%3};"
        : "+f"(c[0]), "+f"(c[1]), "+f"(c[2]), "+f"(c[3])
        : "r"(a[0]), "r"(a[1]), "r"(a[2]), "r"(a[3]), "r"(b[0]), "r"(b[1]));
}

__device__ __forceinline__ void ldsm_x4(uint32_t r[4], uint32_t addr) {
    asm volatile("ldmatrix.sync.aligned.m8n8.x4.shared.b16 {%0,%1,%2,%3}, [%4];"
                 : "=r"(r[0]), "=r"(r[1]), "=r"(r[2]), "=r"(r[3]) : "r"(addr));
}

__device__ __forceinline__ void cpasync16(uint32_t dst, const void* src) {
    asm volatile("cp.async.cg.shared.global [%0], [%1], 16;" :: "r"(dst), "l"(src));
}

__device__ __forceinline__ void msmerge(float& m, float& s, float om, float os) {
    float M = fmaxf(m, om);
    s = s * __expf(m - M) + os * __expf(om - M);
    m = M;
}

// ---------------- shared GEMM mainloop: acc += A(M,K) @ B(N,K)^T tile ----------------
__device__ __forceinline__ void gemm_core(
    const __half* __restrict__ A, const __half* __restrict__ B,
    int lda, int ldb, int tiles, int m0, int n0, float (&acc)[4][8][4])
{
    extern __shared__ __half smh[];
    const uint32_t sbase = (uint32_t)__cvta_generic_to_shared(smh);
    const uint32_t aReg = sbase;
    const uint32_t bReg = sbase + STAGES * ASZH * 2;
    const int tid = threadIdx.x;
    const int wid = tid >> 5, lane = tid & 31;
    const int wm = (wid >> 1) * 64, wn = (wid & 1) * 64;

    uint32_t aAddr[4], bAddr[4];
    {
        const int r = lane & 7;
        const int aRowOff = ((lane >> 3) & 1) * 8 + r;
        const int aChunk = lane >> 4;
#pragma unroll
        for (int mi = 0; mi < 4; mi++)
            aAddr[mi] = aReg + (uint32_t)((wm + mi * 16 + aRowOff) * PH + aChunk * 8) * 2;
        const int bRow = (lane >> 4);
        const int bChunk = (lane >> 3) & 1;
#pragma unroll
        for (int p = 0; p < 4; p++)
            bAddr[p] = bReg + (uint32_t)((wn + (2 * p + bRow) * 8 + r) * PH + bChunk * 8) * 2;
    }

#pragma unroll
    for (int i = 0; i < 4; i++)
#pragma unroll
        for (int j = 0; j < 8; j++)
#pragma unroll
            for (int r = 0; r < 4; r++) acc[i][j][r] = 0.f;

    auto loadTile = [&](int t, int buf) {
        const int k0 = t * BK;
        const uint32_t Ab = aReg + buf * ASZH * 2;
        const uint32_t Bb = bReg + buf * BSZH * 2;
#pragma unroll
        for (int i = 0; i < 4; i++) {
            int idx = i * 128 + tid;
            int row = idx >> 2, seg = idx & 3;
            cpasync16(Ab + (uint32_t)(row * PH + seg * 8) * 2,
                      A + (long long)(m0 + row) * lda + k0 + seg * 8);
        }
#pragma unroll
        for (int i = 0; i < 4; i++) {
            int idx = i * 128 + tid;
            int row = idx >> 2, seg = idx & 3;
            cpasync16(Bb + (uint32_t)(row * PH + seg * 8) * 2,
                      B + (long long)(n0 + row) * ldb + k0 + seg * 8);
        }
        asm volatile("cp.async.commit_group;");
    };

    auto compute = [&](int buf) {
        const uint32_t aOff = buf * ASZH * 2;
        const uint32_t bOff = buf * BSZH * 2;
#pragma unroll
        for (int ks = 0; ks < 2; ks++) {
            uint32_t af[4][4], bf[8][2];
#pragma unroll
            for (int mi = 0; mi < 4; mi++)
                ldsm_x4(af[mi], aAddr[mi] + aOff + ks * 32);
#pragma unroll
            for (int p = 0; p < 4; p++) {
                uint32_t t4[4];
                ldsm_x4(t4, bAddr[p] + bOff + ks * 32);
                bf[2 * p][0] = t4[0]; bf[2 * p][1] = t4[1];
                bf[2 * p + 1][0] = t4[2]; bf[2 * p + 1][1] = t4[3];
            }
#pragma unroll
            for (int mi = 0; mi < 4; mi++)
#pragma unroll
                for (int ni = 0; ni < 8; ni++)
                    mma_f16(acc[mi][ni], af[mi], bf[ni]);
        }
    };

    loadTile(0, 0);
    loadTile(1, 1);
    loadTile(2, 2);
    for (int t = 0; t < tiles; t++) {
        if (t + 2 < tiles) asm volatile("cp.async.wait_group 2;");
        else               asm volatile("cp.async.wait_group 0;");
        __syncthreads();
        if (t + 3 < tiles) loadTile(t + 3, (t + 3) & 3);
        compute(t & 3);
    }
}

// ---------------- conv GEMM: Cf = acc + bias (f32), Ch = half ----------------
__global__ __launch_bounds__(128, 2) void k_conv(
    const __half* __restrict__ A, const __half* __restrict__ B,
    float* __restrict__ Cf, __half* __restrict__ Ch, const float* __restrict__ bias)
{
    const int m0 = blockIdx.y * BM, n0 = blockIdx.x * BN;
    float acc[4][8][4];
    gemm_core(A, B, KIN, KIN, KIN / BK, m0, n0, acc);
    const int tid = threadIdx.x, wid = tid >> 5, lane = tid & 31;
    const int grp = lane >> 2, tig = lane & 3;
    const int wm = (wid >> 1) * 64, wn = (wid & 1) * 64;
#pragma unroll
    for (int mi = 0; mi < 4; mi++) {
        const int r = m0 + wm + mi * 16 + grp;
#pragma unroll
        for (int ni = 0; ni < 8; ni++) {
            const int c = n0 + wn + ni * 8 + tig * 2;
            float bx = bias[c], by = bias[c + 1];
            float2 v0 = {acc[mi][ni][0] + bx, acc[mi][ni][1] + by};
            float2 v1 = {acc[mi][ni][2] + bx, acc[mi][ni][3] + by};
            *(float2*)(Cf + (long long)r * DIM + c) = v0;
            *(float2*)(Cf + (long long)(r + 8) * DIM + c) = v1;
            *(__half2*)(Ch + (long long)r * DIM + c) = __floats2half2_rn(v0.x, v0.y);
            *(__half2*)(Ch + (long long)(r + 8) * DIM + c) = __floats2half2_rn(v1.x, v1.y);
        }
    }
}

// ---------------- merged R/V projection, V written TRANSPOSED directly ----------------
// A: (NB*seq, DIM) half. W: (1024, DIM) = [Wr; Wv]. Rdst: (NB*seq, DIM) half.
// VTdst: per batch (DIM, seq) half.
__global__ __launch_bounds__(128, 2) void k_proj(
    const __half* __restrict__ A, const __half* __restrict__ W,
    __half* __restrict__ Rdst, __half* __restrict__ VTdst, int seq)
{
    const int m0 = blockIdx.y * BM, n0 = blockIdx.x * BN;
    float acc[4][8][4];
    gemm_core(A, W, DIM, DIM, DIM / BK, m0, n0, acc);
    const int tid = threadIdx.x, wid = tid >> 5, lane = tid & 31;
    const int grp = lane >> 2, tig = lane & 3;
    const int wm = (wid >> 1) * 64, wn = (wid & 1) * 64;

    if (n0 < DIM) {
        // R half: normal row-major half store
#pragma unroll
        for (int mi = 0; mi < 4; mi++) {
            const int r = m0 + wm + mi * 16 + grp;
#pragma unroll
            for (int ni = 0; ni < 8; ni++) {
                const int c = n0 + wn + ni * 8 + tig * 2;
                *(__half2*)(Rdst + (long long)r * DIM + c) =
                    __floats2half2_rn(acc[mi][ni][0], acc[mi][ni][1]);
                *(__half2*)(Rdst + (long long)(r + 8) * DIM + c) =
                    __floats2half2_rn(acc[mi][ni][2], acc[mi][ni][3]);
            }
        }
    } else {
        // V half: stage [n][m] in smem, write transposed (E, seq) coalesced
        extern __shared__ __half smh[];
        __syncthreads();                          // mainloop smem no longer needed
        __half* st = smh;                         // 128 * TSTR halves = 34.8KB
#pragma unroll
        for (int mi = 0; mi < 4; mi++) {
            const int ml = wm + mi * 16 + grp;
#pragma unroll
            for (int ni = 0; ni < 8; ni++) {
                const int cl = wn + ni * 8 + tig * 2;
                st[(cl + 0) * TSTR + ml]     = __float2half_rn(acc[mi][ni][0]);
                st[(cl + 1) * TSTR + ml]     = __float2half_rn(acc[mi][ni][1]);
                st[(cl + 0) * TSTR + ml + 8] = __float2half_rn(acc[mi][ni][2]);
                st[(cl + 1) * TSTR + ml + 8] = __float2half_rn(acc[mi][ni][3]);
            }
        }
        __syncthreads();
        const int b = m0 / seq;                   // tile fully inside one batch
        const int s0 = m0 - b * seq;
        const int e0 = n0 - DIM;
        __half* VT = VTdst + (long long)b * DIM * seq;
#pragma unroll
        for (int i = 0; i < 64; i++) {            // 128 rows x 64 half2
            int idx = i * 128 + tid;
            int cl = idx >> 6, pos = (idx & 63) * 2;
            __half2 v = *(__half2*)(st + cl * TSTR + pos);
            *(__half2*)(VT + (long long)(e0 + cl) * seq + s0 + pos) = v;
        }
    }
}

// ---------------- scores GEMM + fused tile-partial stats ----------------
__global__ __launch_bounds__(128, 2) void k_scores(
    const __half* __restrict__ Aall, const __half* __restrict__ Ball, float alpha)
{
    const long long z = blockIdx.z;
    const __half* A = Aall + z * (long long)LSEQ * DIM;
    const __half* B = Ball + z * (long long)SSEQ * DIM;
    float* Cf = g_S + z * (long long)LSEQ * SSEQ;
    const int m0 = blockIdx.y * BM, n0 = blockIdx.x * BN;

    float acc[4][8][4];
    gemm_core(A, B, DIM, DIM, DIM / BK, m0, n0, acc);

    const int tid = threadIdx.x, wid = tid >> 5, lane = tid & 31;
    const int grp = lane >> 2, tig = lane & 3;
    const int wm = (wid >> 1) * 64, wn = (wid & 1) * 64;

#pragma unroll
    for (int mi = 0; mi < 4; mi++)
#pragma unroll
        for (int ni = 0; ni < 8; ni++)
#pragma unroll
            for (int r = 0; r < 4; r++) acc[mi][ni][r] *= alpha;
#pragma unroll
    for (int mi = 0; mi < 4; mi++) {
        const int r = m0 + wm + mi * 16 + grp;
#pragma unroll
        for (int ni = 0; ni < 8; ni++) {
            const int c = n0 + wn + ni * 8 + tig * 2;
            *(float2*)(Cf + (long long)r * SSEQ + c) = make_float2(acc[mi][ni][0], acc[mi][ni][1]);
            *(float2*)(Cf + (long long)(r + 8) * SSEQ + c) = make_float2(acc[mi][ni][2], acc[mi][ni][3]);
        }
    }
    extern __shared__ __half smh[];
    float* smf = (float*)smh;
    __syncthreads();
    // row partials
#pragma unroll
    for (int mi = 0; mi < 4; mi++) {
#pragma unroll
        for (int h = 0; h < 2; h++) {
            float m = -1e30f;
#pragma unroll
            for (int ni = 0; ni < 8; ni++) {
                m = fmaxf(m, acc[mi][ni][2 * h]);
                m = fmaxf(m, acc[mi][ni][2 * h + 1]);
            }
            float s = 0.f;
#pragma unroll
            for (int ni = 0; ni < 8; ni++) {
                s += __expf(acc[mi][ni][2 * h] - m);
                s += __expf(acc[mi][ni][2 * h + 1] - m);
            }
#pragma unroll
            for (int off = 1; off <= 2; off <<= 1) {
                float om = __shfl_xor_sync(0xffffffffu, m, off);
                float os = __shfl_xor_sync(0xffffffffu, s, off);
                msmerge(m, s, om, os);
            }
            if (tig == 0) {
                int lr = mi * 16 + grp + 8 * h;
                smf[(wid * 64 + lr) * 2 + 0] = m;
                smf[(wid * 64 + lr) * 2 + 1] = s;
            }
        }
    }
    __syncthreads();
    if (tid < 128) {
        const int r = tid;
        const int w0 = (r >> 6) * 2, lr = r & 63;
        float m = smf[(w0 * 64 + lr) * 2 + 0];
        float s = smf[(w0 * 64 + lr) * 2 + 1];
        msmerge(m, s, smf[((w0 + 1) * 64 + lr) * 2 + 0], smf[((w0 + 1) * 64 + lr) * 2 + 1]);
        const long long idx = (z * 16 + blockIdx.x) * LSEQ + m0 + r;
        g_prm[idx] = m;
        g_prs[idx] = s;
    }
    __syncthreads();
    // col partials
#pragma unroll
    for (int ni = 0; ni < 8; ni++) {
#pragma unroll
        for (int j = 0; j < 2; j++) {
            float m = -1e30f;
#pragma unroll
            for (int mi = 0; mi < 4; mi++) {
                m = fmaxf(m, acc[mi][ni][j]);
                m = fmaxf(m, acc[mi][ni][2 + j]);
            }
            float s = 0.f;
#pragma unroll
            for (int mi = 0; mi < 4; mi++) {
                s += __expf(acc[mi][ni][j] - m);
                s += __expf(acc[mi][ni][2 + j] - m);
            }
#pragma unroll
            for (int off = 4; off <= 16; off <<= 1) {
                float om = __shfl_xor_sync(0xffffffffu, m, off);
                float os = __shfl_xor_sync(0xffffffffu, s, off);
                msmerge(m, s, om, os);
            }
            if (grp == 0) {
                int lc = ni * 8 + tig * 2 + j;
                smf[(wid * 64 + lc) * 2 + 0] = m;
                smf[(wid * 64 + lc) * 2 + 1] = s;
            }
        }
    }
    __syncthreads();
    if (tid < 128) {
        const int c = tid;
        const int w0 = (c >> 6), lc = c & 63;
        float m = smf[(w0 * 64 + lc) * 2 + 0];
        float s = smf[(w0 * 64 + lc) * 2 + 1];
        msmerge(m, s, smf[((w0 + 2) * 64 + lc) * 2 + 0], smf[((w0 + 2) * 64 + lc) * 2 + 1]);
        const long long idx = (z * 8 + blockIdx.y) * SSEQ + n0 + c;
        g_pcm[idx] = m;
        g_pcs[idx] = s;
    }
}

// ---------------- merged delta GEMM ----------------
__global__ __launch_bounds__(128, 2) void k_delta(
    const float* __restrict__ latents, float* __restrict__ out)
{
    constexpr long long UL = (long long)NB * LSEQ * DIM;
    constexpr long long UT = (long long)NB * SSEQ * DIM;
    constexpr long long CONCAT = UL + UT;

    const long long z = blockIdx.z;
    const __half *A, *Bm;
    const float* addend;
    float *Cf, *Cf2;
    int lda, K, m0;
    if (blockIdx.y < 8) {
        A = g_PrH + z * (long long)LSEQ * SSEQ;  lda = SSEQ; K = SSEQ;
        Bm = g_VtokT + z * (long long)DIM * SSEQ;
        addend = latents + z * (long long)LSEQ * DIM;
        Cf = out + z * (long long)LSEQ * DIM;
        Cf2 = out + CONCAT + z * (long long)(LSEQ + SSEQ) * DIM;
        m0 = blockIdx.y * BM;
    } else {
        A = g_PcTH + z * (long long)SSEQ * LSEQ; lda = LSEQ; K = LSEQ;
        Bm = g_VlatT + z * (long long)DIM * LSEQ;
        addend = g_tok + z * (long long)SSEQ * DIM;
        Cf = out + UL + z * (long long)SSEQ * DIM;
        Cf2 = out + CONCAT + (long long)LSEQ * DIM + z * (long long)(LSEQ + SSEQ) * DIM;
        m0 = (blockIdx.y - 8) * BM;
    }
    const int n0 = blockIdx.x * BN;

    float acc[4][8][4];
    gemm_core(A, Bm, lda, lda, K / BK, m0, n0, acc);

    const int tid = threadIdx.x, wid = tid >> 5, lane = tid & 31;
    const int grp = lane >> 2, tig = lane & 3;
    const int wm = (wid >> 1) * 64, wn = (wid & 1) * 64;
#pragma unroll
    for (int mi = 0; mi < 4; mi++) {
        const int r = m0 + wm + mi * 16 + grp;
#pragma unroll
        for (int ni = 0; ni < 8; ni++) {
            const int c = n0 + wn + ni * 8 + tig * 2;
            float2 a0 = *(const float2*)(addend + (long long)r * DIM + c);
            float2 a1 = *(const float2*)(addend + (long long)(r + 8) * DIM + c);
            float2 v0 = {acc[mi][ni][0] + a0.x, acc[mi][ni][1] + a0.y};
            float2 v1 = {acc[mi][ni][2] + a1.x, acc[mi][ni][3] + a1.y};
            *(float2*)(Cf  + (long long)r * DIM + c) = v0;
            *(float2*)(Cf  + (long long)(r + 8) * DIM + c) = v1;
            *(float2*)(Cf2 + (long long)r * DIM + c) = v0;
            *(float2*)(Cf2 + (long long)(r + 8) * DIM + c) = v1;
        }
    }
}

// ---------------- prep kernels ----------------
__global__ void k_prep_w(const float* __restrict__ w, __half* __restrict__ wc) {
    int i = blockIdx.x * 256 + threadIdx.x;
    if (i < DIM * KIN) {
        int e = i / KIN;
        int r = i - e * KIN;
        int t = r / TOKD;
        int c = r - t * TOKD;
        wc[i] = __float2half_rn(w[e * KIN + c * 5 + t]);
    }
}
__global__ void k_prep_wr(const float* __restrict__ w0, const float* __restrict__ w1,
                          const float* __restrict__ w2, const float* __restrict__ w3,
                          __half* __restrict__ out) {
    int i = blockIdx.x * 256 + threadIdx.x;
    if (i < DIM * DIM) {
        out[i]                 = __float2half_rn(w0[i]);   // Wlat
        out[i + DIM * DIM]     = __float2half_rn(w1[i]);   // Wvlat
        out[i + 2 * DIM * DIM] = __float2half_rn(w2[i]);   // Wtok
        out[i + 3 * DIM * DIM] = __float2half_rn(w3[i]);   // Wvtok
    }
}
__global__ void k_tohalf(const float* __restrict__ s, __half* __restrict__ d, long long n) {
    long long i = ((long long)blockIdx.x * 256 + threadIdx.x) * 4;
    if (i < n) {
        float4 v = *(const float4*)(s + i);
        *(__half2*)(d + i)     = __floats2half2_rn(v.x, v.y);
        *(__half2*)(d + i + 2) = __floats2half2_rn(v.z, v.w);
    }
}

// ---------------- merged stat combine (rows then cols by range) ----------------
__global__ void k_comb(float* __restrict__ rmax, float* __restrict__ rinv,
                       float* __restrict__ cmax, float* __restrict__ cinv) {
    const int idx = blockIdx.x * 256 + threadIdx.x;
    if (idx < NB * LSEQ) {
        const int b = idx >> 10, l = idx & 1023;
        float m = -1e30f;
#pragma unroll
        for (int t = 0; t < 16; t++) m = fmaxf(m, g_prm[(b * 16 + t) * LSEQ + l]);
        float s = 0.f;
#pragma unroll
        for (int t = 0; t < 16; t++)
            s += g_prs[(b * 16 + t) * LSEQ + l] * __expf(g_prm[(b * 16 + t) * LSEQ + l] - m);
        rmax[idx] = m;
        rinv[idx] = 1.f / s;
    } else {
        const int j = idx - NB * LSEQ;           // 0 .. NB*SSEQ-1
        const int b = j >> 11, s0 = j & 2047;
        float m = -1e30f;
#pragma unroll
        for (int t = 0; t < 8; t++) m = fmaxf(m, g_pcm[(b * 8 + t) * SSEQ + s0]);
        float s = 0.f;
#pragma unroll
        for (int t = 0; t < 8; t++)
            s += g_pcs[(b * 8 + t) * SSEQ + s0] * __expf(g_pcm[(b * 8 + t) * SSEQ + s0] - m);
        cmax[j] = m;
        cinv[j] = 1.f / s;
    }
}

// ---------------- apply both softmaxes -> half ----------------
__global__ __launch_bounds__(256) void k_softmax_apply(
    const float* __restrict__ A, __half* __restrict__ Pr, __half* __restrict__ PcT,
    const float* __restrict__ rmax, const float* __restrict__ rinv,
    const float* __restrict__ cmax, const float* __restrict__ cinv)
{
    __shared__ float tile[32][33];
    const int b = blockIdx.z;
    const int s0 = blockIdx.x * 32, l0 = blockIdx.y * 32;
    const float* Ab = A + (long long)b * LSEQ * SSEQ;
    __half* Prb = Pr + (long long)b * LSEQ * SSEQ;
    __half* Pcb = PcT + (long long)b * SSEQ * LSEQ;
    const int tx = threadIdx.x & 31, ty = threadIdx.x >> 5;

    const float cm = cmax[b * SSEQ + s0 + tx];
    const float ci = cinv[b * SSEQ + s0 + tx];
#pragma unroll
    for (int i = 0; i < 4; i++) {
        const int l = l0 + ty + i * 8;
        float v = Ab[(long long)l * SSEQ + s0 + tx];
        Prb[(long long)l * SSEQ + s0 + tx] =
            __float2half_rn(__expf(v - rmax[b * LSEQ + l]) * rinv[b * LSEQ + l]);
        tile[ty + i * 8][tx] = __expf(v - cm) * ci;
    }
    __syncthreads();
#pragma unroll
    for (int i = 0; i < 4; i++) {
        const int s = s0 + ty + i * 8;
        Pcb[(long long)s * LSEQ + l0 + tx] = __float2half_rn(tile[tx][ty + i * 8]);
    }
}

// ---------------- launch ----------------
extern "C" void kernel_launch(void* const* d_in, const int* in_sizes, int n_in,
                              void* d_out, int out_size) {
    const float* latents = (const float*)d_in[0];
    const float* tokens  = (const float*)d_in[1];
    const float* W_lat   = (const float*)d_in[2];
    const float* W_tok   = (const float*)d_in[3];
    const float* W_vlat  = (const float*)d_in[4];
    const float* W_vtok  = (const float*)d_in[5];
    const float* conv_w  = (const float*)d_in[6];
    const float* conv_b  = (const float*)d_in[7];
    float* out = (float*)d_out;

    __half *wcH, *wrH, *toksH, *latH, *tokH, *rlatH, *rtokH, *vlatT, *vtokT, *prH, *pcTH;
    float *tok, *smat, *rmax, *rinv, *cmax, *cinv;
    cudaGetSymbolAddress((void**)&wcH,   g_WcH);
    cudaGetSymbolAddress((void**)&wrH,   g_WrH);
    cudaGetSymbolAddress((void**)&toksH, g_toksH);
    cudaGetSymbolAddress((void**)&latH,  g_latH);
    cudaGetSymbolAddress((void**)&tok,   g_tok);
    cudaGetSymbolAddress((void**)&tokH,  g_tokH);
    cudaGetSymbolAddress((void**)&rlatH, g_RlatH);
    cudaGetSymbolAddress((void**)&rtokH, g_RtokH);
    cudaGetSymbolAddress((void**)&vlatT, g_VlatT);
    cudaGetSymbolAddress((void**)&vtokT, g_VtokT);
    cudaGetSymbolAddress((void**)&prH,   g_PrH);
    cudaGetSymbolAddress((void**)&pcTH,  g_PcTH);
    cudaGetSymbolAddress((void**)&smat,  g_S);
    cudaGetSymbolAddress((void**)&rmax,  g_rmax);
    cudaGetSymbolAddress((void**)&rinv,  g_rinv);
    cudaGetSymbolAddress((void**)&cmax,  g_cmax);
    cudaGetSymbolAddress((void**)&cinv,  g_cinv);

    cudaFuncSetAttribute(k_conv,   cudaFuncAttributeMaxDynamicSharedMemorySize, SM_BYTES);
    cudaFuncSetAttribute(k_proj,   cudaFuncAttributeMaxDynamicSharedMemorySize, SM_BYTES);
    cudaFuncSetAttribute(k_scores, cudaFuncAttributeMaxDynamicSharedMemorySize, SM_BYTES);
    cudaFuncSetAttribute(k_delta,  cudaFuncAttributeMaxDynamicSharedMemorySize, SM_BYTES);

    const long long NTOK = (long long)NB * TOKS * TOKD;
    const long long NLAT = (long long)NB * LSEQ * DIM;
    k_tohalf<<<(int)(NTOK / 4 / 256), 256>>>(tokens, toksH, NTOK);
    k_tohalf<<<(int)(NLAT / 4 / 256), 256>>>(latents, latH, NLAT);
    k_prep_w<<<(DIM * KIN + 255) / 256, 256>>>(conv_w, wcH);
    k_prep_wr<<<(DIM * DIM + 255) / 256, 256>>>(W_lat, W_vlat, W_tok, W_vtok, wrH);

    // conv as GEMM
    k_conv<<<dim3(DIM / BN, (NB * SSEQ) / BM), 128, SM_BYTES>>>(toksH, wcH, tok, tokH, conv_b);

    // merged projections; V halves written transposed directly
    k_proj<<<dim3(2 * DIM / BN, (NB * LSEQ) / BM), 128, SM_BYTES>>>(
        latH, wrH, rlatH, vlatT, LSEQ);
    k_proj<<<dim3(2 * DIM / BN, (NB * SSEQ) / BM), 128, SM_BYTES>>>(
        tokH, wrH + 2 * DIM * DIM, rtokH, vtokT, SSEQ);

    // scores + fused stats
    const float scale = 0.044194173824159216f;
    k_scores<<<dim3(SSEQ / BN, LSEQ / BM, NB), 128, SM_BYTES>>>(rlatH, rtokH, scale);

    // combine + apply
    k_comb<<<(NB * LSEQ + NB * SSEQ) / 256, 256>>>(rmax, rinv, cmax, cinv);
    k_softmax_apply<<<dim3(SSEQ / 32, LSEQ / 32, NB), 256>>>(
        smat, prH, pcTH, rmax, rinv, cmax, cinv);

    // merged delta
    k_delta<<<dim3(DIM / BN, 24, NB), 128, SM_BYTES>>>(latents, out);
}

// round 12
// speedup vs baseline: 2.3771x; 1.0360x over previous
#include <cuda_runtime.h>
#include <cuda_fp16.h>
#include <math.h>
#include <stdint.h>

// ---------------- problem constants ----------------
#define NB   8
#define LSEQ 1024
#define SSEQ 2048
#define DIM  512
#define TOKD 256
#define KIN  1280
#define TOKS 10240

// ---------------- scratch ----------------
__device__ __align__(256) __half g_WcH  [DIM * KIN];
__device__ __align__(256) __half g_WrH  [4 * DIM * DIM];   // [Wlat, Wvlat, Wtok, Wvtok]
__device__ __align__(256) __half g_toksH[NB * TOKS * TOKD];
__device__ __align__(256) __half g_latH [NB * LSEQ * DIM];
__device__ __align__(256) float  g_tok  [NB * SSEQ * DIM];
__device__ __align__(256) __half g_tokH [NB * SSEQ * DIM];
__device__ __align__(256) __half g_RlatH[NB * LSEQ * DIM];
__device__ __align__(256) __half g_RtokH[NB * SSEQ * DIM];
__device__ __align__(256) __half g_VlatT[NB * DIM * LSEQ];   // (E, L)
__device__ __align__(256) __half g_VtokT[NB * DIM * SSEQ];   // (E, S)
__device__ __align__(256) float  g_S    [NB * LSEQ * SSEQ];
__device__ __align__(256) __half g_PrH  [NB * LSEQ * SSEQ];
__device__ __align__(256) __half g_PcTH [NB * SSEQ * LSEQ];
__device__ __align__(256) float  g_rmax [NB * LSEQ];
__device__ __align__(256) float  g_rinv [NB * LSEQ];
__device__ __align__(256) float  g_cmax [NB * SSEQ];
__device__ __align__(256) float  g_cinv [NB * SSEQ];
__device__ __align__(256) float  g_prm  [NB * 16 * LSEQ];
__device__ __align__(256) float  g_prs  [NB * 16 * LSEQ];
__device__ __align__(256) float  g_pcm  [NB * 8 * SSEQ];
__device__ __align__(256) float  g_pcs  [NB * 8 * SSEQ];

// ---------------- GEMM config ----------------
#define BM 128
#define BN 128
#define BK 32
#define PH 40
#define STAGES 4
#define ASZH (BM * PH)
#define BSZH (BN * PH)
#define SM_BYTES (STAGES * (ASZH + BSZH) * 2)   // 81920
#define TSTR 136

__device__ __forceinline__ void mma_f16(float c[4], const uint32_t a[4], const uint32_t b[2]) {
    asm volatile(
        "mma.sync.aligned.m16n8k16.row.col.f32.f16.f16.f32 "
        "{%0,%1,%2,%3}, {%4,%5,%6,%7}, {%8,%9}, {%0,%1,%2,%3};"
        : "+f"(c[0]), "+f"(c[1]), "+f"(c[2]), "+f"(c[3])
        : "r"(a[0]), "r"(a[1]), "r"(a[2]), "r"(a[3]), "r"(b[0]), "r"(b[1]));
}

__device__ __forceinline__ void ldsm_x4(uint32_t r[4], uint32_t addr) {
    asm volatile("ldmatrix.sync.aligned.m8n8.x4.shared.b16 {%0,%1,%2,%3}, [%4];"
                 : "=r"(r[0]), "=r"(r[1]), "=r"(r[2]), "=r"(r[3]) : "r"(addr));
}

__device__ __forceinline__ void cpasync16(uint32_t dst, const void* src) {
    asm volatile("cp.async.cg.shared.global [%0], [%1], 16;" :: "r"(dst), "l"(src));
}

__device__ __forceinline__ void msmerge(float& m, float& s, float om, float os) {
    float M = fmaxf(m, om);
    s = s * __expf(m - M) + os * __expf(om - M);
    m = M;
}

// ---------------- shared GEMM mainloop ----------------
__device__ __forceinline__ void gemm_core(
    const __half* __restrict__ A, const __half* __restrict__ B,
    int lda, int ldb, int tiles, int m0, int n0, float (&acc)[4][8][4])
{
    extern __shared__ __half smh[];
    const uint32_t sbase = (uint32_t)__cvta_generic_to_shared(smh);
    const uint32_t aReg = sbase;
    const uint32_t bReg = sbase + STAGES * ASZH * 2;
    const int tid = threadIdx.x;
    const int wid = tid >> 5, lane = tid & 31;
    const int wm = (wid >> 1) * 64, wn = (wid & 1) * 64;

    uint32_t aAddr[4], bAddr[4];
    {
        const int r = lane & 7;
        const int aRowOff = ((lane >> 3) & 1) * 8 + r;
        const int aChunk = lane >> 4;
#pragma unroll
        for (int mi = 0; mi < 4; mi++)
            aAddr[mi] = aReg + (uint32_t)((wm + mi * 16 + aRowOff) * PH + aChunk * 8) * 2;
        const int bRow = (lane >> 4);
        const int bChunk = (lane >> 3) & 1;
#pragma unroll
        for (int p = 0; p < 4; p++)
            bAddr[p] = bReg + (uint32_t)((wn + (2 * p + bRow) * 8 + r) * PH + bChunk * 8) * 2;
    }

#pragma unroll
    for (int i = 0; i < 4; i++)
#pragma unroll
        for (int j = 0; j < 8; j++)
#pragma unroll
            for (int r = 0; r < 4; r++) acc[i][j][r] = 0.f;

    auto loadTile = [&](int t, int buf) {
        const int k0 = t * BK;
        const uint32_t Ab = aReg + buf * ASZH * 2;
        const uint32_t Bb = bReg + buf * BSZH * 2;
#pragma unroll
        for (int i = 0; i < 4; i++) {
            int idx = i * 128 + tid;
            int row = idx >> 2, seg = idx & 3;
            cpasync16(Ab + (uint32_t)(row * PH + seg * 8) * 2,
                      A + (long long)(m0 + row) * lda + k0 + seg * 8);
        }
#pragma unroll
        for (int i = 0; i < 4; i++) {
            int idx = i * 128 + tid;
            int row = idx >> 2, seg = idx & 3;
            cpasync16(Bb + (uint32_t)(row * PH + seg * 8) * 2,
                      B + (long long)(n0 + row) * ldb + k0 + seg * 8);
        }
        asm volatile("cp.async.commit_group;");
    };

    auto compute = [&](int buf) {
        const uint32_t aOff = buf * ASZH * 2;
        const uint32_t bOff = buf * BSZH * 2;
#pragma unroll
        for (int ks = 0; ks < 2; ks++) {
            uint32_t af[4][4], bf[8][2];
#pragma unroll
            for (int mi = 0; mi < 4; mi++)
                ldsm_x4(af[mi], aAddr[mi] + aOff + ks * 32);
#pragma unroll
            for (int p = 0; p < 4; p++) {
                uint32_t t4[4];
                ldsm_x4(t4, bAddr[p] + bOff + ks * 32);
                bf[2 * p][0] = t4[0]; bf[2 * p][1] = t4[1];
                bf[2 * p + 1][0] = t4[2]; bf[2 * p + 1][1] = t4[3];
            }
#pragma unroll
            for (int mi = 0; mi < 4; mi++)
#pragma unroll
                for (int ni = 0; ni < 8; ni++)
                    mma_f16(acc[mi][ni], af[mi], bf[ni]);
        }
    };

    loadTile(0, 0);
    loadTile(1, 1);
    loadTile(2, 2);
    for (int t = 0; t < tiles; t++) {
        if (t + 2 < tiles) asm volatile("cp.async.wait_group 2;");
        else               asm volatile("cp.async.wait_group 0;");
        __syncthreads();
        if (t + 3 < tiles) loadTile(t + 3, (t + 3) & 3);
        compute(t & 3);
    }
}

// ---------------- conv GEMM ----------------
__global__ __launch_bounds__(128, 2) void k_conv(
    const __half* __restrict__ A, const __half* __restrict__ B,
    float* __restrict__ Cf, __half* __restrict__ Ch, const float* __restrict__ bias)
{
    const int m0 = blockIdx.y * BM, n0 = blockIdx.x * BN;
    float acc[4][8][4];
    gemm_core(A, B, KIN, KIN, KIN / BK, m0, n0, acc);
    const int tid = threadIdx.x, wid = tid >> 5, lane = tid & 31;
    const int grp = lane >> 2, tig = lane & 3;
    const int wm = (wid >> 1) * 64, wn = (wid & 1) * 64;
#pragma unroll
    for (int mi = 0; mi < 4; mi++) {
        const int r = m0 + wm + mi * 16 + grp;
#pragma unroll
        for (int ni = 0; ni < 8; ni++) {
            const int c = n0 + wn + ni * 8 + tig * 2;
            float bx = bias[c], by = bias[c + 1];
            float2 v0 = {acc[mi][ni][0] + bx, acc[mi][ni][1] + by};
            float2 v1 = {acc[mi][ni][2] + bx, acc[mi][ni][3] + by};
            *(float2*)(Cf + (long long)r * DIM + c) = v0;
            *(float2*)(Cf + (long long)(r + 8) * DIM + c) = v1;
            *(__half2*)(Ch + (long long)r * DIM + c) = __floats2half2_rn(v0.x, v0.y);
            *(__half2*)(Ch + (long long)(r + 8) * DIM + c) = __floats2half2_rn(v1.x, v1.y);
        }
    }
}

// ---------------- merged R/V projection, V written transposed ----------------
__global__ __launch_bounds__(128, 2) void k_proj(
    const __half* __restrict__ A, const __half* __restrict__ W,
    __half* __restrict__ Rdst, __half* __restrict__ VTdst, int seq)
{
    const int m0 = blockIdx.y * BM, n0 = blockIdx.x * BN;
    float acc[4][8][4];
    gemm_core(A, W, DIM, DIM, DIM / BK, m0, n0, acc);
    const int tid = threadIdx.x, wid = tid >> 5, lane = tid & 31;
    const int grp = lane >> 2, tig = lane & 3;
    const int wm = (wid >> 1) * 64, wn = (wid & 1) * 64;

    if (n0 < DIM) {
#pragma unroll
        for (int mi = 0; mi < 4; mi++) {
            const int r = m0 + wm + mi * 16 + grp;
#pragma unroll
            for (int ni = 0; ni < 8; ni++) {
                const int c = n0 + wn + ni * 8 + tig * 2;
                *(__half2*)(Rdst + (long long)r * DIM + c) =
                    __floats2half2_rn(acc[mi][ni][0], acc[mi][ni][1]);
                *(__half2*)(Rdst + (long long)(r + 8) * DIM + c) =
                    __floats2half2_rn(acc[mi][ni][2], acc[mi][ni][3]);
            }
        }
    } else {
        extern __shared__ __half smh[];
        __syncthreads();
        __half* st = smh;
#pragma unroll
        for (int mi = 0; mi < 4; mi++) {
            const int ml = wm + mi * 16 + grp;
#pragma unroll
            for (int ni = 0; ni < 8; ni++) {
                const int cl = wn + ni * 8 + tig * 2;
                st[(cl + 0) * TSTR + ml]     = __float2half_rn(acc[mi][ni][0]);
                st[(cl + 1) * TSTR + ml]     = __float2half_rn(acc[mi][ni][1]);
                st[(cl + 0) * TSTR + ml + 8] = __float2half_rn(acc[mi][ni][2]);
                st[(cl + 1) * TSTR + ml + 8] = __float2half_rn(acc[mi][ni][3]);
            }
        }
        __syncthreads();
        const int b = m0 / seq;
        const int s0 = m0 - b * seq;
        const int e0 = n0 - DIM;
        __half* VT = VTdst + (long long)b * DIM * seq;
#pragma unroll
        for (int i = 0; i < 64; i++) {
            int idx = i * 128 + tid;
            int cl = idx >> 6, pos = (idx & 63) * 2;
            __half2 v = *(__half2*)(st + cl * TSTR + pos);
            *(__half2*)(VT + (long long)(e0 + cl) * seq + s0 + pos) = v;
        }
    }
}

// ---------------- scores GEMM + fused tile-partial stats ----------------
__global__ __launch_bounds__(128, 2) void k_scores(
    const __half* __restrict__ Aall, const __half* __restrict__ Ball, float alpha)
{
    const long long z = blockIdx.z;
    const __half* A = Aall + z * (long long)LSEQ * DIM;
    const __half* B = Ball + z * (long long)SSEQ * DIM;
    float* Cf = g_S + z * (long long)LSEQ * SSEQ;
    const int m0 = blockIdx.y * BM, n0 = blockIdx.x * BN;

    float acc[4][8][4];
    gemm_core(A, B, DIM, DIM, DIM / BK, m0, n0, acc);

    const int tid = threadIdx.x, wid = tid >> 5, lane = tid & 31;
    const int grp = lane >> 2, tig = lane & 3;
    const int wm = (wid >> 1) * 64, wn = (wid & 1) * 64;

#pragma unroll
    for (int mi = 0; mi < 4; mi++)
#pragma unroll
        for (int ni = 0; ni < 8; ni++)
#pragma unroll
            for (int r = 0; r < 4; r++) acc[mi][ni][r] *= alpha;
#pragma unroll
    for (int mi = 0; mi < 4; mi++) {
        const int r = m0 + wm + mi * 16 + grp;
#pragma unroll
        for (int ni = 0; ni < 8; ni++) {
            const int c = n0 + wn + ni * 8 + tig * 2;
            *(float2*)(Cf + (long long)r * SSEQ + c) = make_float2(acc[mi][ni][0], acc[mi][ni][1]);
            *(float2*)(Cf + (long long)(r + 8) * SSEQ + c) = make_float2(acc[mi][ni][2], acc[mi][ni][3]);
        }
    }
    extern __shared__ __half smh[];
    float* smf = (float*)smh;
    __syncthreads();
    // row partials
#pragma unroll
    for (int mi = 0; mi < 4; mi++) {
#pragma unroll
        for (int h = 0; h < 2; h++) {
            float m = -1e30f;
#pragma unroll
            for (int ni = 0; ni < 8; ni++) {
                m = fmaxf(m, acc[mi][ni][2 * h]);
                m = fmaxf(m, acc[mi][ni][2 * h + 1]);
            }
            float s = 0.f;
#pragma unroll
            for (int ni = 0; ni < 8; ni++) {
                s += __expf(acc[mi][ni][2 * h] - m);
                s += __expf(acc[mi][ni][2 * h + 1] - m);
            }
#pragma unroll
            for (int off = 1; off <= 2; off <<= 1) {
                float om = __shfl_xor_sync(0xffffffffu, m, off);
                float os = __shfl_xor_sync(0xffffffffu, s, off);
                msmerge(m, s, om, os);
            }
            if (tig == 0) {
                int lr = mi * 16 + grp + 8 * h;
                smf[(wid * 64 + lr) * 2 + 0] = m;
                smf[(wid * 64 + lr) * 2 + 1] = s;
            }
        }
    }
    __syncthreads();
    if (tid < 128) {
        const int r = tid;
        const int w0 = (r >> 6) * 2, lr = r & 63;
        float m = smf[(w0 * 64 + lr) * 2 + 0];
        float s = smf[(w0 * 64 + lr) * 2 + 1];
        msmerge(m, s, smf[((w0 + 1) * 64 + lr) * 2 + 0], smf[((w0 + 1) * 64 + lr) * 2 + 1]);
        const long long idx = (z * 16 + blockIdx.x) * LSEQ + m0 + r;
        g_prm[idx] = m;
        g_prs[idx] = s;
    }
    __syncthreads();
    // col partials
#pragma unroll
    for (int ni = 0; ni < 8; ni++) {
#pragma unroll
        for (int j = 0; j < 2; j++) {
            float m = -1e30f;
#pragma unroll
            for (int mi = 0; mi < 4; mi++) {
                m = fmaxf(m, acc[mi][ni][j]);
                m = fmaxf(m, acc[mi][ni][2 + j]);
            }
            float s = 0.f;
#pragma unroll
            for (int mi = 0; mi < 4; mi++) {
                s += __expf(acc[mi][ni][j] - m);
                s += __expf(acc[mi][ni][2 + j] - m);
            }
#pragma unroll
            for (int off = 4; off <= 16; off <<= 1) {
                float om = __shfl_xor_sync(0xffffffffu, m, off);
                float os = __shfl_xor_sync(0xffffffffu, s, off);
                msmerge(m, s, om, os);
            }
            if (grp == 0) {
                int lc = ni * 8 + tig * 2 + j;
                smf[(wid * 64 + lc) * 2 + 0] = m;
                smf[(wid * 64 + lc) * 2 + 1] = s;
            }
        }
    }
    __syncthreads();
    if (tid < 128) {
        const int c = tid;
        const int w0 = (c >> 6), lc = c & 63;
        float m = smf[(w0 * 64 + lc) * 2 + 0];
        float s = smf[(w0 * 64 + lc) * 2 + 1];
        msmerge(m, s, smf[((w0 + 2) * 64 + lc) * 2 + 0], smf[((w0 + 2) * 64 + lc) * 2 + 1]);
        const long long idx = (z * 8 + blockIdx.y) * SSEQ + n0 + c;
        g_pcm[idx] = m;
        g_pcs[idx] = s;
    }
}

// ---------------- merged delta GEMM ----------------
__global__ __launch_bounds__(128, 2) void k_delta(
    const float* __restrict__ latents, float* __restrict__ out)
{
    constexpr long long UL = (long long)NB * LSEQ * DIM;
    constexpr long long UT = (long long)NB * SSEQ * DIM;
    constexpr long long CONCAT = UL + UT;

    const long long z = blockIdx.z;
    const __half *A, *Bm;
    const float* addend;
    float *Cf, *Cf2;
    int lda, K, m0;
    if (blockIdx.y < 8) {
        A = g_PrH + z * (long long)LSEQ * SSEQ;  lda = SSEQ; K = SSEQ;
        Bm = g_VtokT + z * (long long)DIM * SSEQ;
        addend = latents + z * (long long)LSEQ * DIM;
        Cf = out + z * (long long)LSEQ * DIM;
        Cf2 = out + CONCAT + z * (long long)(LSEQ + SSEQ) * DIM;
        m0 = blockIdx.y * BM;
    } else {
        A = g_PcTH + z * (long long)SSEQ * LSEQ; lda = LSEQ; K = LSEQ;
        Bm = g_VlatT + z * (long long)DIM * LSEQ;
        addend = g_tok + z * (long long)SSEQ * DIM;
        Cf = out + UL + z * (long long)SSEQ * DIM;
        Cf2 = out + CONCAT + (long long)LSEQ * DIM + z * (long long)(LSEQ + SSEQ) * DIM;
        m0 = (blockIdx.y - 8) * BM;
    }
    const int n0 = blockIdx.x * BN;

    float acc[4][8][4];
    gemm_core(A, Bm, lda, lda, K / BK, m0, n0, acc);

    const int tid = threadIdx.x, wid = tid >> 5, lane = tid & 31;
    const int grp = lane >> 2, tig = lane & 3;
    const int wm = (wid >> 1) * 64, wn = (wid & 1) * 64;
#pragma unroll
    for (int mi = 0; mi < 4; mi++) {
        const int r = m0 + wm + mi * 16 + grp;
#pragma unroll
        for (int ni = 0; ni < 8; ni++) {
            const int c = n0 + wn + ni * 8 + tig * 2;
            float2 a0 = *(const float2*)(addend + (long long)r * DIM + c);
            float2 a1 = *(const float2*)(addend + (long long)(r + 8) * DIM + c);
            float2 v0 = {acc[mi][ni][0] + a0.x, acc[mi][ni][1] + a0.y};
            float2 v1 = {acc[mi][ni][2] + a1.x, acc[mi][ni][3] + a1.y};
            *(float2*)(Cf  + (long long)r * DIM + c) = v0;
            *(float2*)(Cf  + (long long)(r + 8) * DIM + c) = v1;
            *(float2*)(Cf2 + (long long)r * DIM + c) = v0;
            *(float2*)(Cf2 + (long long)(r + 8) * DIM + c) = v1;
        }
    }
}

// ---------------- prep kernels ----------------
__global__ void k_prep_w(const float* __restrict__ w, __half* __restrict__ wc) {
    int i = blockIdx.x * 256 + threadIdx.x;
    if (i < DIM * KIN) {
        int e = i / KIN;
        int r = i - e * KIN;
        int t = r / TOKD;
        int c = r - t * TOKD;
        wc[i] = __float2half_rn(w[e * KIN + c * 5 + t]);
    }
}
__global__ void k_prep_wr(const float* __restrict__ w0, const float* __restrict__ w1,
                          const float* __restrict__ w2, const float* __restrict__ w3,
                          __half* __restrict__ out) {
    int i = blockIdx.x * 256 + threadIdx.x;
    if (i < DIM * DIM) {
        out[i]                 = __float2half_rn(w0[i]);
        out[i + DIM * DIM]     = __float2half_rn(w1[i]);
        out[i + 2 * DIM * DIM] = __float2half_rn(w2[i]);
        out[i + 3 * DIM * DIM] = __float2half_rn(w3[i]);
    }
}
__global__ void k_tohalf(const float* __restrict__ s, __half* __restrict__ d, long long n) {
    long long i = ((long long)blockIdx.x * 256 + threadIdx.x) * 4;
    if (i < n) {
        float4 v = *(const float4*)(s + i);
        *(__half2*)(d + i)     = __floats2half2_rn(v.x, v.y);
        *(__half2*)(d + i + 2) = __floats2half2_rn(v.z, v.w);
    }
}

// ---------------- merged stat combine ----------------
__global__ void k_comb(float* __restrict__ rmax, float* __restrict__ rinv,
                       float* __restrict__ cmax, float* __restrict__ cinv) {
    const int idx = blockIdx.x * 256 + threadIdx.x;
    if (idx < NB * LSEQ) {
        const int b = idx >> 10, l = idx & 1023;
        float m = -1e30f;
#pragma unroll
        for (int t = 0; t < 16; t++) m = fmaxf(m, g_prm[(b * 16 + t) * LSEQ + l]);
        float s = 0.f;
#pragma unroll
        for (int t = 0; t < 16; t++)
            s += g_prs[(b * 16 + t) * LSEQ + l] * __expf(g_prm[(b * 16 + t) * LSEQ + l] - m);
        rmax[idx] = m;
        rinv[idx] = 1.f / s;
    } else {
        const int j = idx - NB * LSEQ;
        const int b = j >> 11, s0 = j & 2047;
        float m = -1e30f;
#pragma unroll
        for (int t = 0; t < 8; t++) m = fmaxf(m, g_pcm[(b * 8 + t) * SSEQ + s0]);
        float s = 0.f;
#pragma unroll
        for (int t = 0; t < 8; t++)
            s += g_pcs[(b * 8 + t) * SSEQ + s0] * __expf(g_pcm[(b * 8 + t) * SSEQ + s0] - m);
        cmax[j] = m;
        cinv[j] = 1.f / s;
    }
}

// ---------------- apply both softmaxes -> half (vectorized) ----------------
// block handles 32 l x 64 s with 256 threads
__global__ __launch_bounds__(256) void k_softmax_apply(
    const float* __restrict__ A, __half* __restrict__ Pr, __half* __restrict__ PcT,
    const float* __restrict__ rmax, const float* __restrict__ rinv,
    const float* __restrict__ cmax, const float* __restrict__ cinv)
{
    __shared__ float tile[64][33];   // [s_local][l_local], exp_col values
    const int b = blockIdx.z;
    const int s0 = blockIdx.x * 64, l0 = blockIdx.y * 32;
    const float* Ab = A + (long long)b * LSEQ * SSEQ;
    __half* Prb = Pr + (long long)b * LSEQ * SSEQ;
    __half* Pcb = PcT + (long long)b * SSEQ * LSEQ;
    const int lane = threadIdx.x & 31, ty = threadIdx.x >> 5;   // ty in [0,8)

    const int sc = s0 + 2 * lane;
    const float2 cm = *(const float2*)(cmax + b * SSEQ + sc);
    const float2 ci = *(const float2*)(cinv + b * SSEQ + sc);
#pragma unroll
    for (int i = 0; i < 4; i++) {
        const int l = l0 + ty + i * 8;
        const float rm = rmax[b * LSEQ + l];
        const float riv = rinv[b * LSEQ + l];
        float2 v = *(const float2*)(Ab + (long long)l * SSEQ + sc);
        *(__half2*)(Prb + (long long)l * SSEQ + sc) =
            __floats2half2_rn(__expf(v.x - rm) * riv, __expf(v.y - rm) * riv);
        tile[2 * lane][ty + i * 8]     = __expf(v.x - cm.x) * ci.x;
        tile[2 * lane + 1][ty + i * 8] = __expf(v.y - cm.y) * ci.y;
    }
    __syncthreads();
    const int sl = threadIdx.x >> 2;
    const int lo = (threadIdx.x & 3) * 8;
    __half* dst = Pcb + (long long)(s0 + sl) * LSEQ + l0 + lo;
#pragma unroll
    for (int j = 0; j < 8; j += 2)
        *(__half2*)(dst + j) = __floats2half2_rn(tile[sl][lo + j], tile[sl][lo + j + 1]);
}

// ---------------- launch ----------------
extern "C" void kernel_launch(void* const* d_in, const int* in_sizes, int n_in,
                              void* d_out, int out_size) {
    const float* latents = (const float*)d_in[0];
    const float* tokens  = (const float*)d_in[1];
    const float* W_lat   = (const float*)d_in[2];
    const float* W_tok   = (const float*)d_in[3];
    const float* W_vlat  = (const float*)d_in[4];
    const float* W_vtok  = (const float*)d_in[5];
    const float* conv_w  = (const float*)d_in[6];
    const float* conv_b  = (const float*)d_in[7];
    float* out = (float*)d_out;

    __half *wcH, *wrH, *toksH, *latH, *tokH, *rlatH, *rtokH, *vlatT, *vtokT, *prH, *pcTH;
    float *tok, *smat, *rmax, *rinv, *cmax, *cinv;
    cudaGetSymbolAddress((void**)&wcH,   g_WcH);
    cudaGetSymbolAddress((void**)&wrH,   g_WrH);
    cudaGetSymbolAddress((void**)&toksH, g_toksH);
    cudaGetSymbolAddress((void**)&latH,  g_latH);
    cudaGetSymbolAddress((void**)&tok,   g_tok);
    cudaGetSymbolAddress((void**)&tokH,  g_tokH);
    cudaGetSymbolAddress((void**)&rlatH, g_RlatH);
    cudaGetSymbolAddress((void**)&rtokH, g_RtokH);
    cudaGetSymbolAddress((void**)&vlatT, g_VlatT);
    cudaGetSymbolAddress((void**)&vtokT, g_VtokT);
    cudaGetSymbolAddress((void**)&prH,   g_PrH);
    cudaGetSymbolAddress((void**)&pcTH,  g_PcTH);
    cudaGetSymbolAddress((void**)&smat,  g_S);
    cudaGetSymbolAddress((void**)&rmax,  g_rmax);
    cudaGetSymbolAddress((void**)&rinv,  g_rinv);
    cudaGetSymbolAddress((void**)&cmax,  g_cmax);
    cudaGetSymbolAddress((void**)&cinv,  g_cinv);

    cudaFuncSetAttribute(k_conv,   cudaFuncAttributeMaxDynamicSharedMemorySize, SM_BYTES);
    cudaFuncSetAttribute(k_proj,   cudaFuncAttributeMaxDynamicSharedMemorySize, SM_BYTES);
    cudaFuncSetAttribute(k_scores, cudaFuncAttributeMaxDynamicSharedMemorySize, SM_BYTES);
    cudaFuncSetAttribute(k_delta,  cudaFuncAttributeMaxDynamicSharedMemorySize, SM_BYTES);

    // one-time side stream + events (host objects; no device allocation)
    static cudaStream_t s1 = nullptr;
    static cudaEvent_t eRoot = nullptr, eA = nullptr, eB = nullptr;
    if (s1 == nullptr) {
        cudaStreamCreateWithFlags(&s1, cudaStreamNonBlocking);
        cudaEventCreateWithFlags(&eRoot, cudaEventDisableTiming);
        cudaEventCreateWithFlags(&eA, cudaEventDisableTiming);
        cudaEventCreateWithFlags(&eB, cudaEventDisableTiming);
    }

    const long long NTOK = (long long)NB * TOKS * TOKD;
    const long long NLAT = (long long)NB * LSEQ * DIM;

    // fork: side stream handles latent-side prep + projection
    cudaEventRecord(eRoot, 0);
    cudaStreamWaitEvent(s1, eRoot, 0);

    // side stream: latents->half, proj weights->half, lat projections
    k_tohalf<<<(int)(NLAT / 4 / 256), 256, 0, s1>>>(latents, latH, NLAT);
    k_prep_wr<<<(DIM * DIM + 255) / 256, 256, 0, s1>>>(W_lat, W_vlat, W_tok, W_vtok, wrH);
    cudaEventRecord(eA, s1);                      // wrH ready
    k_proj<<<dim3(2 * DIM / BN, (NB * LSEQ) / BM), 128, SM_BYTES, s1>>>(
        latH, wrH, rlatH, vlatT, LSEQ);
    cudaEventRecord(eB, s1);                      // rlatH, vlatT ready

    // main stream: token-side prep + conv
    k_tohalf<<<(int)(NTOK / 4 / 256), 256>>>(tokens, toksH, NTOK);
    k_prep_w<<<(DIM * KIN + 255) / 256, 256>>>(conv_w, wcH);
    k_conv<<<dim3(DIM / BN, (NB * SSEQ) / BM), 128, SM_BYTES>>>(toksH, wcH, tok, tokH, conv_b);

    cudaStreamWaitEvent(0, eA, 0);                // need wrH for proj_tok
    k_proj<<<dim3(2 * DIM / BN, (NB * SSEQ) / BM), 128, SM_BYTES>>>(
        tokH, wrH + 2 * DIM * DIM, rtokH, vtokT, SSEQ);

    cudaStreamWaitEvent(0, eB, 0);                // join side stream before scores
    const float scale = 0.044194173824159216f;
    k_scores<<<dim3(SSEQ / BN, LSEQ / BM, NB), 128, SM_BYTES>>>(rlatH, rtokH, scale);

    k_comb<<<(NB * LSEQ + NB * SSEQ) / 256, 256>>>(rmax, rinv, cmax, cinv);
    k_softmax_apply<<<dim3(SSEQ / 64, LSEQ / 32, NB), 256>>>(
        smat, prH, pcTH, rmax, rinv, cmax, cinv);

    k_delta<<<dim3(DIM / BN, 24, NB), 128, SM_BYTES>>>(latents, out);
}